// round 1
// baseline (speedup 1.0000x reference)
#include <cuda_runtime.h>
#include <cuda_bf16.h>
#include <math.h>

#define Nn 4096
#define Ee 4096
#define NHID 512
#define NHEAD 8
#define DKh 64
#define NLAYER 4
#define NCLASS 16

// ---------------- scratch (static device globals; no allocation) ----------------
__device__ float g_G[(size_t)Nn * Nn];                    // 64 MB
__device__ float g_S[(size_t)NHEAD * Nn * Nn];            // 512 MB
__device__ float g_x[Nn * NHID];
__device__ float g_q[Nn * NHID];
__device__ float g_k[Nn * NHID];
__device__ float g_v[Nn * NHID];
__device__ float g_gv[Nn * NHID];
__device__ float g_ctx[Nn * NHID];
__device__ float g_pre[Nn * NHID];
__device__ float g_DV[Nn];
__device__ float g_DEpart[32 * Ee];
__device__ float g_dv2[Nn];
__device__ float g_invDE[Ee];

// ---------------- degrees ----------------
__global__ void row_sums_k(const float* __restrict__ H) {
    int t = threadIdx.x;
    const float* row = H + (size_t)blockIdx.x * Ee;
    float s = 0.f;
    for (int e = t; e < Ee; e += 256) s += row[e];
    __shared__ float red[256];
    red[t] = s; __syncthreads();
    for (int w = 128; w > 0; w >>= 1) { if (t < w) red[t] += red[t + w]; __syncthreads(); }
    if (t == 0) g_DV[blockIdx.x] = red[0];
}

__global__ void col_part_k(const float* __restrict__ H) {
    int e = blockIdx.x * 256 + threadIdx.x;
    int r0 = blockIdx.y * 128;
    float s = 0.f;
    for (int n = r0; n < r0 + 128; n++) s += H[(size_t)n * Ee + e];
    g_DEpart[blockIdx.y * Ee + e] = s;
}

__global__ void finalize_deg_k() {
    int i = blockIdx.x * 256 + threadIdx.x;
    if (i < Nn) {
        g_dv2[i] = (i == 0) ? 1.0f : rsqrtf(g_DV[i]);
    }
    if (i < Ee) {
        float s = 0.f;
        for (int p = 0; p < 32; p++) s += g_DEpart[p * Ee + i];
        g_invDE[i] = 1.0f / s;
    }
}

// ---------------- Laplacian GEMM: G = dv2 . (H diag(1/DE) H^T) . dv2 ----------------
#define BM 64
#define BN 64
#define BK 16

__global__ void gemmG_k(const float* __restrict__ H) {
    __shared__ float As[BM][BK + 1];
    __shared__ float Bs[BK][BN];
    int t = threadIdx.x;
    int tx = t & 15, ty = t >> 4;
    int m0 = blockIdx.y * BM, n0 = blockIdx.x * BN;
    float acc[4][4] = {};
    for (int k0 = 0; k0 < Ee; k0 += BK) {
#pragma unroll
        for (int u = 0; u < 4; u++) {
            int l = t * 4 + u;
            int m = l >> 4, k = l & 15;
            As[m][k] = H[(size_t)(m0 + m) * Ee + k0 + k] * g_invDE[k0 + k];
        }
#pragma unroll
        for (int u = 0; u < 4; u++) {
            int l = t * 4 + u;
            int n = l >> 4, k = l & 15;
            Bs[k][n] = H[(size_t)(n0 + n) * Ee + k0 + k];
        }
        __syncthreads();
#pragma unroll
        for (int kk = 0; kk < BK; kk++) {
            float a[4], b[4];
#pragma unroll
            for (int i = 0; i < 4; i++) a[i] = As[ty * 4 + i][kk];
#pragma unroll
            for (int j = 0; j < 4; j++) b[j] = Bs[kk][tx * 4 + j];
#pragma unroll
            for (int i = 0; i < 4; i++)
#pragma unroll
                for (int j = 0; j < 4; j++) acc[i][j] += a[i] * b[j];
        }
        __syncthreads();
    }
#pragma unroll
    for (int i = 0; i < 4; i++) {
        int m = m0 + ty * 4 + i;
        float dm = g_dv2[m];
#pragma unroll
        for (int j = 0; j < 4; j++) {
            int n = n0 + tx * 4 + j;
            g_G[(size_t)m * Nn + n] = acc[i][j] * dm * g_dv2[n];
        }
    }
}

// ---------------- generic SGEMM ----------------
// C[m,n] = alpha * sum_k A[m,k]*B(k,n)  (+ bias[n]) (+ addScale*add[m,n])
// TRANSB=false: B row-major [K,N] (ldb);  TRANSB=true: B row-major [N,K] (ldb), i.e. C=A*B^T
template <bool TRANSB>
__global__ void sgemm_k(const float* __restrict__ A, int lda, long long sA,
                        const float* __restrict__ B, int ldb, long long sB,
                        float* __restrict__ C, int ldc, long long sC,
                        const float* __restrict__ bias,
                        const float* __restrict__ add, int ldadd, long long sAdd,
                        float addScale, int K, float alpha) {
    int z = blockIdx.z;
    A += (size_t)z * sA;
    B += (size_t)z * sB;
    C += (size_t)z * sC;
    if (add) add += (size_t)z * sAdd;

    __shared__ float As[BM][BK + 1];
    __shared__ float Bs[BK][BN];
    int t = threadIdx.x;
    int tx = t & 15, ty = t >> 4;
    int m0 = blockIdx.y * BM, n0 = blockIdx.x * BN;
    float acc[4][4] = {};
    for (int k0 = 0; k0 < K; k0 += BK) {
#pragma unroll
        for (int u = 0; u < 4; u++) {
            int l = t * 4 + u;
            int m = l >> 4, k = l & 15;
            As[m][k] = A[(size_t)(m0 + m) * lda + k0 + k];
        }
        if (!TRANSB) {
#pragma unroll
            for (int u = 0; u < 4; u++) {
                int l = t * 4 + u;
                int k = l >> 6, n = l & 63;
                Bs[k][n] = B[(size_t)(k0 + k) * ldb + n0 + n];
            }
        } else {
#pragma unroll
            for (int u = 0; u < 4; u++) {
                int l = t * 4 + u;
                int n = l >> 4, k = l & 15;
                Bs[k][n] = B[(size_t)(n0 + n) * ldb + k0 + k];
            }
        }
        __syncthreads();
#pragma unroll
        for (int kk = 0; kk < BK; kk++) {
            float a[4], b[4];
#pragma unroll
            for (int i = 0; i < 4; i++) a[i] = As[ty * 4 + i][kk];
#pragma unroll
            for (int j = 0; j < 4; j++) b[j] = Bs[kk][tx * 4 + j];
#pragma unroll
            for (int i = 0; i < 4; i++)
#pragma unroll
                for (int j = 0; j < 4; j++) acc[i][j] += a[i] * b[j];
        }
        __syncthreads();
    }
#pragma unroll
    for (int i = 0; i < 4; i++) {
        int m = m0 + ty * 4 + i;
#pragma unroll
        for (int j = 0; j < 4; j++) {
            int n = n0 + tx * 4 + j;
            float v = alpha * acc[i][j];
            if (bias) v += bias[n];
            if (add) v += addScale * add[(size_t)m * ldadd + n];
            C[(size_t)m * ldc + n] = v;
        }
    }
}

// ---------------- row softmax over 4096 ----------------
__global__ void softmax_k(float* __restrict__ S) {
    int t = threadIdx.x;
    float* row = S + (size_t)blockIdx.x * Nn;
    float v[16];
    float mx = -INFINITY;
#pragma unroll
    for (int i = 0; i < 16; i++) { v[i] = row[t + i * 256]; mx = fmaxf(mx, v[i]); }
    __shared__ float red[256];
    red[t] = mx; __syncthreads();
    for (int w = 128; w > 0; w >>= 1) { if (t < w) red[t] = fmaxf(red[t], red[t + w]); __syncthreads(); }
    mx = red[0]; __syncthreads();
    float sum = 0.f;
#pragma unroll
    for (int i = 0; i < 16; i++) { v[i] = __expf(v[i] - mx); sum += v[i]; }
    red[t] = sum; __syncthreads();
    for (int w = 128; w > 0; w >>= 1) { if (t < w) red[t] += red[t + w]; __syncthreads(); }
    float inv = 1.0f / red[0];
#pragma unroll
    for (int i = 0; i < 16; i++) row[t + i * 256] = v[i] * inv;
}

// ---------------- layernorm + prelu ----------------
__global__ void ln_prelu_k(const float* __restrict__ in, float* __restrict__ out,
                           const float* __restrict__ g, const float* __restrict__ b,
                           const float* __restrict__ aptr) {
    int t = threadIdx.x;
    const float* row = in + (size_t)blockIdx.x * NHID;
    float x0 = row[t], x1 = row[t + 256];
    __shared__ float red[256];
    red[t] = x0 + x1; __syncthreads();
    for (int w = 128; w > 0; w >>= 1) { if (t < w) red[t] += red[t + w]; __syncthreads(); }
    float mu = red[0] * (1.0f / NHID);
    __syncthreads();
    float d0 = x0 - mu, d1 = x1 - mu;
    red[t] = d0 * d0 + d1 * d1; __syncthreads();
    for (int w = 128; w > 0; w >>= 1) { if (t < w) red[t] += red[t + w]; __syncthreads(); }
    float inv = rsqrtf(red[0] * (1.0f / NHID) + 1e-5f);
    float a = *aptr;
    float y0 = d0 * inv * g[t] + b[t];
    float y1 = d1 * inv * g[t + 256] + b[t + 256];
    float* orow = out + (size_t)blockIdx.x * NHID;
    orow[t] = (y0 >= 0.f) ? y0 : a * y0;
    orow[t + 256] = (y1 >= 0.f) ? y1 : a * y1;
}

// ---------------- classifier + log_softmax ----------------
__global__ void cls_k(const float* __restrict__ x, const float* __restrict__ w,
                      const float* __restrict__ bias, float* __restrict__ out) {
    __shared__ float xs[NHID];
    __shared__ float lg[NCLASS];
    int t = threadIdx.x;  // 128
    const float* row = x + (size_t)blockIdx.x * NHID;
    for (int i = t; i < NHID; i += 128) xs[i] = row[i];
    __syncthreads();
    if (t < NCLASS) {
        float s = bias[t];
        for (int k = 0; k < NHID; k++) s += xs[k] * w[k * NCLASS + t];
        lg[t] = s;
    }
    __syncthreads();
    if (t < NCLASS) {
        float mx = -INFINITY;
        for (int c = 0; c < NCLASS; c++) mx = fmaxf(mx, lg[c]);
        float sum = 0.f;
        for (int c = 0; c < NCLASS; c++) sum += __expf(lg[c] - mx);
        out[(size_t)blockIdx.x * NCLASS + t] = lg[t] - mx - logf(sum);
    }
}

// ---------------- host launcher ----------------
extern "C" void kernel_launch(void* const* d_in, const int* in_sizes, int n_in,
                              void* d_out, int out_size) {
    const float* X0     = (const float*)d_in[0];
    const float* Hm     = (const float*)d_in[1];
    const float* w_feat = (const float*)d_in[2];
    const float* b_feat = (const float*)d_in[3];
    const float* Wq     = (const float*)d_in[4];
    const float* bq     = (const float*)d_in[5];
    const float* Wk     = (const float*)d_in[6];
    const float* bk     = (const float*)d_in[7];
    const float* Wv     = (const float*)d_in[8];
    const float* bv     = (const float*)d_in[9];
    const float* Wo     = (const float*)d_in[10];
    const float* bo     = (const float*)d_in[11];
    const float* ln_g   = (const float*)d_in[12];
    const float* ln_b   = (const float*)d_in[13];
    const float* prelu_a= (const float*)d_in[14];
    const float* w_cls  = (const float*)d_in[15];
    const float* b_cls  = (const float*)d_in[16];
    float* out = (float*)d_out;

    float *G_, *S_, *x_, *q_, *k_, *v_, *gv_, *ctx_, *pre_;
    cudaGetSymbolAddress((void**)&G_, g_G);
    cudaGetSymbolAddress((void**)&S_, g_S);
    cudaGetSymbolAddress((void**)&x_, g_x);
    cudaGetSymbolAddress((void**)&q_, g_q);
    cudaGetSymbolAddress((void**)&k_, g_k);
    cudaGetSymbolAddress((void**)&v_, g_v);
    cudaGetSymbolAddress((void**)&gv_, g_gv);
    cudaGetSymbolAddress((void**)&ctx_, g_ctx);
    cudaGetSymbolAddress((void**)&pre_, g_pre);

    // degrees + Laplacian
    row_sums_k<<<Nn, 256>>>(Hm);
    col_part_k<<<dim3(Ee / 256, 32), 256>>>(Hm);
    finalize_deg_k<<<Nn / 256, 256>>>();
    gemmG_k<<<dim3(Nn / BN, Nn / BM), 256>>>(Hm);

    // feature embed: x = X0 @ w_feat + b_feat
    sgemm_k<false><<<dim3(NHID / BN, Nn / BM), 256>>>(
        X0, NHID, 0, w_feat, NHID, 0, x_, NHID, 0,
        b_feat, nullptr, 0, 0, 0.f, NHID, 1.f);

    const long long HS = (long long)Nn * Nn;
    for (int i = 0; i < NLAYER; i++) {
        const float* Wqi = Wq + (size_t)i * NHID * NHID;
        const float* Wki = Wk + (size_t)i * NHID * NHID;
        const float* Wvi = Wv + (size_t)i * NHID * NHID;
        const float* Woi = Wo + (size_t)i * NHID * NHID;

        sgemm_k<false><<<dim3(NHID / BN, Nn / BM), 256>>>(
            x_, NHID, 0, Wqi, NHID, 0, q_, NHID, 0,
            bq + i * NHID, nullptr, 0, 0, 0.f, NHID, 1.f);
        sgemm_k<false><<<dim3(NHID / BN, Nn / BM), 256>>>(
            x_, NHID, 0, Wki, NHID, 0, k_, NHID, 0,
            bk + i * NHID, nullptr, 0, 0, 0.f, NHID, 1.f);
        sgemm_k<false><<<dim3(NHID / BN, Nn / BM), 256>>>(
            x_, NHID, 0, Wvi, NHID, 0, v_, NHID, 0,
            bv + i * NHID, nullptr, 0, 0, 0.f, NHID, 1.f);

        // GV = G @ v   [4096,512]
        sgemm_k<false><<<dim3(NHID / BN, Nn / BM), 256>>>(
            G_, Nn, 0, v_, NHID, 0, gv_, NHID, 0,
            nullptr, nullptr, 0, 0, 0.f, Nn, 1.f);

        // scores[h] = (q_h @ k_h^T) / 8
        sgemm_k<true><<<dim3(Nn / BN, Nn / BM, NHEAD), 256>>>(
            q_, NHID, DKh, k_, NHID, DKh, S_, Nn, HS,
            nullptr, nullptr, 0, 0, 0.f, DKh, 0.125f);

        softmax_k<<<NHEAD * Nn, 256>>>(S_);

        // ctx_h = 0.5 * attn_h @ v_h + 0.5 * GV_h
        sgemm_k<false><<<dim3(1, Nn / BM, NHEAD), 256>>>(
            S_, Nn, HS, v_, NHID, DKh, ctx_, NHID, DKh,
            nullptr, gv_, NHID, DKh, 0.5f, Nn, 0.5f);

        // pre = ctx @ Wo + bo + x
        sgemm_k<false><<<dim3(NHID / BN, Nn / BM), 256>>>(
            ctx_, NHID, 0, Woi, NHID, 0, pre_, NHID, 0,
            bo + i * NHID, x_, NHID, 0, 1.f, NHID, 1.f);

        ln_prelu_k<<<Nn, 256>>>(pre_, x_, ln_g + i * NHID, ln_b + i * NHID, prelu_a + i);
    }

    cls_k<<<Nn, 128>>>(x_, w_cls, b_cls, out);
}

// round 4
// speedup vs baseline: 1.7040x; 1.7040x over previous
#include <cuda_runtime.h>
#include <cuda_bf16.h>
#include <math.h>
#include <stdint.h>

#define Nn 4096
#define Ee 4096
#define NHID 512
#define NHEAD 8
#define DKh 64
#define NLAYER 4
#define NCLASS 16

// ---------------- scratch ----------------
__device__ float g_S[(size_t)NHEAD * Nn * Nn];            // 512 MB scores
__device__ float g_x[Nn * NHID];
__device__ float g_q[Nn * NHID];
__device__ float g_k[Nn * NHID];
__device__ float g_v[Nn * NHID];
__device__ float g_w[Ee * NHID];
__device__ float g_gv[Nn * NHID];
__device__ float g_ctx[Nn * NHID];
__device__ float g_pre[Nn * NHID];
__device__ float g_DV[Nn];
__device__ float g_DEpart[32 * Ee];
__device__ float g_dv2[Nn];
__device__ float g_invDE[Ee];

// ---------------- degrees ----------------
__global__ void row_sums_k(const float* __restrict__ H) {
    int t = threadIdx.x;
    const float* row = H + (size_t)blockIdx.x * Ee;
    float s = 0.f;
    for (int e = t; e < Ee; e += 256) s += row[e];
    __shared__ float red[256];
    red[t] = s; __syncthreads();
    for (int w = 128; w > 0; w >>= 1) { if (t < w) red[t] += red[t + w]; __syncthreads(); }
    if (t == 0) g_DV[blockIdx.x] = red[0];
}

__global__ void col_part_k(const float* __restrict__ H) {
    int e = blockIdx.x * 256 + threadIdx.x;
    int r0 = blockIdx.y * 128;
    float s = 0.f;
    for (int n = r0; n < r0 + 128; n++) s += H[(size_t)n * Ee + e];
    g_DEpart[blockIdx.y * Ee + e] = s;
}

__global__ void finalize_deg_k() {
    int i = blockIdx.x * 256 + threadIdx.x;
    if (i < Nn) g_dv2[i] = (i == 0) ? 1.0f : rsqrtf(g_DV[i]);
    if (i < Ee) {
        float s = 0.f;
        for (int p = 0; p < 32; p++) s += g_DEpart[p * Ee + i];
        g_invDE[i] = 1.0f / s;
    }
}

// ---------------- split-tf32 tensor-core GEMM ----------------
// C = alpha * op(A) @ op(B)  (+bias[n]) (+addScale*add) (* rowScale[m] in epilogue)
// TA=0: A row-major [M,K]; TA=1: A row-major [K,M]
// TB=0: B row-major [K,N]; TB=1: B row-major [N,K] (C = A @ B^T)
// kScale: optional per-k scale folded into B loads.
#define BM 128
#define BN 128
#define BK 32

__device__ __forceinline__ float tf32_rna(float x) {
    float r;
    asm("cvt.rna.tf32.f32 %0, %1;" : "=f"(r) : "f"(x));
    return r;
}

__device__ __forceinline__ void mma_tf32(float c[4], uint32_t a0, uint32_t a1,
                                         uint32_t a2, uint32_t a3,
                                         uint32_t b0, uint32_t b1) {
    asm volatile(
        "mma.sync.aligned.m16n8k8.row.col.f32.tf32.tf32.f32 "
        "{%0,%1,%2,%3},{%4,%5,%6,%7},{%8,%9},{%0,%1,%2,%3};"
        : "+f"(c[0]), "+f"(c[1]), "+f"(c[2]), "+f"(c[3])
        : "r"(a0), "r"(a1), "r"(a2), "r"(a3), "r"(b0), "r"(b1));
}

template <int TA, int TB>
__global__ __launch_bounds__(256) void tc_gemm(
    const float* __restrict__ A, int lda, long long sA,
    const float* __restrict__ B, int ldb, long long sB,
    float* __restrict__ C, int ldc, long long sC,
    const float* __restrict__ bias,
    const float* __restrict__ add, int ldadd, long long sAdd, float addScale,
    const float* __restrict__ kScale, const float* __restrict__ rowScale,
    int K, int Nmat, float alpha) {
    int z = blockIdx.z;
    A += (size_t)z * sA;
    B += (size_t)z * sB;
    C += (size_t)z * sC;
    if (add) add += (size_t)z * sAdd;

    __shared__ float As[BK][BM + 4];
    __shared__ float Bs[BK][BN + 4];

    int t = threadIdx.x;
    int lane = t & 31;
    int warp = t >> 5;
    int wm = (warp >> 2) * 64;
    int wn = (warp & 3) * 32;
    int m0 = blockIdx.y * BM;
    int n0 = blockIdx.x * BN;

    float acc[4][4][4];
#pragma unroll
    for (int i = 0; i < 4; i++)
#pragma unroll
        for (int j = 0; j < 4; j++)
#pragma unroll
            for (int r = 0; r < 4; r++) acc[i][j][r] = 0.f;

    for (int k0 = 0; k0 < K; k0 += BK) {
        // ---- load A tile -> As[k][m]
        if (TA == 0) {
            int row = t >> 3, kq = t & 7;
#pragma unroll
            for (int p = 0; p < 4; p++) {
                int m = row + p * 32;
                float4 a = *(const float4*)&A[(size_t)(m0 + m) * lda + k0 + kq * 4];
                As[kq * 4 + 0][m] = a.x;
                As[kq * 4 + 1][m] = a.y;
                As[kq * 4 + 2][m] = a.z;
                As[kq * 4 + 3][m] = a.w;
            }
        } else {
            int kk = t >> 5, mq = t & 31;
#pragma unroll
            for (int p = 0; p < 4; p++) {
                int k = kk + p * 8;
                float4 a = *(const float4*)&A[(size_t)(k0 + k) * lda + m0 + mq * 4];
                *(float4*)&As[k][mq * 4] = a;
            }
        }
        // ---- load B tile -> Bs[k][n]
        if (TB == 0) {
            int kk = t >> 5, nq = t & 31;
#pragma unroll
            for (int p = 0; p < 4; p++) {
                int k = kk + p * 8;
                int col = n0 + nq * 4;
                float4 b = make_float4(0.f, 0.f, 0.f, 0.f);
                if (col < Nmat) b = *(const float4*)&B[(size_t)(k0 + k) * ldb + col];
                if (kScale) {
                    float s = kScale[k0 + k];
                    b.x *= s; b.y *= s; b.z *= s; b.w *= s;
                }
                *(float4*)&Bs[k][nq * 4] = b;
            }
        } else {
            int row = t >> 3, kq = t & 7;
#pragma unroll
            for (int p = 0; p < 4; p++) {
                int n = row + p * 32;
                float4 b = make_float4(0.f, 0.f, 0.f, 0.f);
                if (n0 + n < Nmat) b = *(const float4*)&B[(size_t)(n0 + n) * ldb + k0 + kq * 4];
                if (kScale) {
                    b.x *= kScale[k0 + kq * 4 + 0];
                    b.y *= kScale[k0 + kq * 4 + 1];
                    b.z *= kScale[k0 + kq * 4 + 2];
                    b.w *= kScale[k0 + kq * 4 + 3];
                }
                Bs[kq * 4 + 0][n] = b.x;
                Bs[kq * 4 + 1][n] = b.y;
                Bs[kq * 4 + 2][n] = b.z;
                Bs[kq * 4 + 3][n] = b.w;
            }
        }
        __syncthreads();

#pragma unroll
        for (int kk = 0; kk < 4; kk++) {
            int kb = kk * 8 + (lane & 3);
            uint32_t ahi[4][4], alo[4][4], bhi[4][2], blo[4][2];
#pragma unroll
            for (int mi = 0; mi < 4; mi++) {
                int r = wm + mi * 16 + (lane >> 2);
                float x0 = As[kb][r], x1 = As[kb][r + 8];
                float x2 = As[kb + 4][r], x3 = As[kb + 4][r + 8];
                float h0 = tf32_rna(x0), h1 = tf32_rna(x1), h2 = tf32_rna(x2), h3 = tf32_rna(x3);
                ahi[mi][0] = __float_as_uint(h0);
                ahi[mi][1] = __float_as_uint(h1);
                ahi[mi][2] = __float_as_uint(h2);
                ahi[mi][3] = __float_as_uint(h3);
                alo[mi][0] = __float_as_uint(tf32_rna(x0 - h0));
                alo[mi][1] = __float_as_uint(tf32_rna(x1 - h1));
                alo[mi][2] = __float_as_uint(tf32_rna(x2 - h2));
                alo[mi][3] = __float_as_uint(tf32_rna(x3 - h3));
            }
#pragma unroll
            for (int ni = 0; ni < 4; ni++) {
                int c = wn + ni * 8 + (lane >> 2);
                float y0 = Bs[kb][c], y1 = Bs[kb + 4][c];
                float g0 = tf32_rna(y0), g1 = tf32_rna(y1);
                bhi[ni][0] = __float_as_uint(g0);
                bhi[ni][1] = __float_as_uint(g1);
                blo[ni][0] = __float_as_uint(tf32_rna(y0 - g0));
                blo[ni][1] = __float_as_uint(tf32_rna(y1 - g1));
            }
#pragma unroll
            for (int mi = 0; mi < 4; mi++)
#pragma unroll
                for (int ni = 0; ni < 4; ni++) {
                    mma_tf32(acc[mi][ni], ahi[mi][0], ahi[mi][1], ahi[mi][2], ahi[mi][3],
                             bhi[ni][0], bhi[ni][1]);
                    mma_tf32(acc[mi][ni], ahi[mi][0], ahi[mi][1], ahi[mi][2], ahi[mi][3],
                             blo[ni][0], blo[ni][1]);
                    mma_tf32(acc[mi][ni], alo[mi][0], alo[mi][1], alo[mi][2], alo[mi][3],
                             bhi[ni][0], bhi[ni][1]);
                }
        }
        __syncthreads();
    }

    // ---- epilogue
#pragma unroll
    for (int mi = 0; mi < 4; mi++) {
        int r0 = m0 + wm + mi * 16 + (lane >> 2);
        int r1 = r0 + 8;
        float rs0 = rowScale ? rowScale[r0] : 1.f;
        float rs1 = rowScale ? rowScale[r1] : 1.f;
#pragma unroll
        for (int ni = 0; ni < 4; ni++) {
            int c0 = n0 + wn + ni * 8 + (lane & 3) * 2;
            int c1 = c0 + 1;
            if (c0 < Nmat) {
                float v00 = alpha * acc[mi][ni][0] * rs0;
                float v01 = alpha * acc[mi][ni][1] * rs0;
                float v10 = alpha * acc[mi][ni][2] * rs1;
                float v11 = alpha * acc[mi][ni][3] * rs1;
                if (bias) { v00 += bias[c0]; v01 += bias[c1]; v10 += bias[c0]; v11 += bias[c1]; }
                if (add) {
                    v00 += addScale * add[(size_t)r0 * ldadd + c0];
                    v01 += addScale * add[(size_t)r0 * ldadd + c1];
                    v10 += addScale * add[(size_t)r1 * ldadd + c0];
                    v11 += addScale * add[(size_t)r1 * ldadd + c1];
                }
                C[(size_t)r0 * ldc + c0] = v00;
                C[(size_t)r0 * ldc + c1] = v01;
                C[(size_t)r1 * ldc + c0] = v10;
                C[(size_t)r1 * ldc + c1] = v11;
            }
        }
    }
}

// ---------------- row softmax over 4096 ----------------
__global__ void softmax_k(float* __restrict__ S) {
    int t = threadIdx.x;
    float* row = S + (size_t)blockIdx.x * Nn;
    float v[16];
    float mx = -INFINITY;
#pragma unroll
    for (int i = 0; i < 16; i++) { v[i] = row[t + i * 256]; mx = fmaxf(mx, v[i]); }
    __shared__ float red[256];
    red[t] = mx; __syncthreads();
    for (int w = 128; w > 0; w >>= 1) { if (t < w) red[t] = fmaxf(red[t], red[t + w]); __syncthreads(); }
    mx = red[0]; __syncthreads();
    float sum = 0.f;
#pragma unroll
    for (int i = 0; i < 16; i++) { v[i] = __expf(v[i] - mx); sum += v[i]; }
    red[t] = sum; __syncthreads();
    for (int w = 128; w > 0; w >>= 1) { if (t < w) red[t] += red[t + w]; __syncthreads(); }
    float inv = 1.0f / red[0];
#pragma unroll
    for (int i = 0; i < 16; i++) row[t + i * 256] = v[i] * inv;
}

// ---------------- layernorm + prelu ----------------
__global__ void ln_prelu_k(const float* __restrict__ in, float* __restrict__ out,
                           const float* __restrict__ g, const float* __restrict__ b,
                           const float* __restrict__ aptr) {
    int t = threadIdx.x;
    const float* row = in + (size_t)blockIdx.x * NHID;
    float x0 = row[t], x1 = row[t + 256];
    __shared__ float red[256];
    red[t] = x0 + x1; __syncthreads();
    for (int w = 128; w > 0; w >>= 1) { if (t < w) red[t] += red[t + w]; __syncthreads(); }
    float mu = red[0] * (1.0f / NHID);
    __syncthreads();
    float d0 = x0 - mu, d1 = x1 - mu;
    red[t] = d0 * d0 + d1 * d1; __syncthreads();
    for (int w = 128; w > 0; w >>= 1) { if (t < w) red[t] += red[t + w]; __syncthreads(); }
    float inv = rsqrtf(red[0] * (1.0f / NHID) + 1e-5f);
    float a = *aptr;
    float y0 = d0 * inv * g[t] + b[t];
    float y1 = d1 * inv * g[t + 256] + b[t + 256];
    float* orow = out + (size_t)blockIdx.x * NHID;
    orow[t] = (y0 >= 0.f) ? y0 : a * y0;
    orow[t + 256] = (y1 >= 0.f) ? y1 : a * y1;
}

// ---------------- classifier + log_softmax ----------------
__global__ void cls_k(const float* __restrict__ x, const float* __restrict__ w,
                      const float* __restrict__ bias, float* __restrict__ out) {
    __shared__ float xs[NHID];
    __shared__ float lg[NCLASS];
    int t = threadIdx.x;  // 128
    const float* row = x + (size_t)blockIdx.x * NHID;
    for (int i = t; i < NHID; i += 128) xs[i] = row[i];
    __syncthreads();
    if (t < NCLASS) {
        float s = bias[t];
        for (int k = 0; k < NHID; k++) s += xs[k] * w[k * NCLASS + t];
        lg[t] = s;
    }
    __syncthreads();
    if (t < NCLASS) {
        float mx = -INFINITY;
        for (int c = 0; c < NCLASS; c++) mx = fmaxf(mx, lg[c]);
        float sum = 0.f;
        for (int c = 0; c < NCLASS; c++) sum += __expf(lg[c] - mx);
        out[(size_t)blockIdx.x * NCLASS + t] = lg[t] - mx - logf(sum);
    }
}

// ---------------- host launcher ----------------
extern "C" void kernel_launch(void* const* d_in, const int* in_sizes, int n_in,
                              void* d_out, int out_size) {
    const float* X0     = (const float*)d_in[0];
    const float* Hm     = (const float*)d_in[1];
    const float* w_feat = (const float*)d_in[2];
    const float* b_feat = (const float*)d_in[3];
    const float* Wq     = (const float*)d_in[4];
    const float* bq     = (const float*)d_in[5];
    const float* Wk     = (const float*)d_in[6];
    const float* bk     = (const float*)d_in[7];
    const float* Wv     = (const float*)d_in[8];
    const float* bv     = (const float*)d_in[9];
    const float* Wo     = (const float*)d_in[10];
    const float* bo     = (const float*)d_in[11];
    const float* ln_g   = (const float*)d_in[12];
    const float* ln_b   = (const float*)d_in[13];
    const float* prelu_a= (const float*)d_in[14];
    const float* w_cls  = (const float*)d_in[15];
    const float* b_cls  = (const float*)d_in[16];
    float* out = (float*)d_out;

    float *S_, *x_, *q_, *k_, *v_, *w_, *gv_, *ctx_, *pre_, *dv2_, *invDE_;
    cudaGetSymbolAddress((void**)&S_, g_S);
    cudaGetSymbolAddress((void**)&x_, g_x);
    cudaGetSymbolAddress((void**)&q_, g_q);
    cudaGetSymbolAddress((void**)&k_, g_k);
    cudaGetSymbolAddress((void**)&v_, g_v);
    cudaGetSymbolAddress((void**)&w_, g_w);
    cudaGetSymbolAddress((void**)&gv_, g_gv);
    cudaGetSymbolAddress((void**)&ctx_, g_ctx);
    cudaGetSymbolAddress((void**)&pre_, g_pre);
    cudaGetSymbolAddress((void**)&dv2_, g_dv2);
    cudaGetSymbolAddress((void**)&invDE_, g_invDE);

    row_sums_k<<<Nn, 256>>>(Hm);
    col_part_k<<<dim3(Ee / 256, 32), 256>>>(Hm);
    finalize_deg_k<<<Nn / 256, 256>>>();

    dim3 gHid(NHID / BN, Nn / BM);

    // x = X0 @ w_feat + b_feat
    tc_gemm<0, 0><<<gHid, 256>>>(X0, NHID, 0, w_feat, NHID, 0, x_, NHID, 0,
                                 b_feat, nullptr, 0, 0, 0.f, nullptr, nullptr,
                                 NHID, NHID, 1.f);

    const long long HS = (long long)Nn * Nn;
    for (int i = 0; i < NLAYER; i++) {
        const float* Wqi = Wq + (size_t)i * NHID * NHID;
        const float* Wki = Wk + (size_t)i * NHID * NHID;
        const float* Wvi = Wv + (size_t)i * NHID * NHID;
        const float* Woi = Wo + (size_t)i * NHID * NHID;

        tc_gemm<0, 0><<<gHid, 256>>>(x_, NHID, 0, Wqi, NHID, 0, q_, NHID, 0,
                                     bq + i * NHID, nullptr, 0, 0, 0.f, nullptr, nullptr,
                                     NHID, NHID, 1.f);
        tc_gemm<0, 0><<<gHid, 256>>>(x_, NHID, 0, Wki, NHID, 0, k_, NHID, 0,
                                     bk + i * NHID, nullptr, 0, 0, 0.f, nullptr, nullptr,
                                     NHID, NHID, 1.f);
        tc_gemm<0, 0><<<gHid, 256>>>(x_, NHID, 0, Wvi, NHID, 0, v_, NHID, 0,
                                     bv + i * NHID, nullptr, 0, 0, 0.f, nullptr, nullptr,
                                     NHID, NHID, 1.f);

        // w = H^T @ (dv2 * v)    [E, NHID]
        tc_gemm<1, 0><<<gHid, 256>>>(Hm, Ee, 0, v_, NHID, 0, w_, NHID, 0,
                                     nullptr, nullptr, 0, 0, 0.f, dv2_, nullptr,
                                     Nn, NHID, 1.f);
        // gv = dv2 * (H @ (invDE * w))   [N, NHID]
        tc_gemm<0, 0><<<gHid, 256>>>(Hm, Ee, 0, w_, NHID, 0, gv_, NHID, 0,
                                     nullptr, nullptr, 0, 0, 0.f, invDE_, dv2_,
                                     Ee, NHID, 1.f);

        // scores[h] = (q_h @ k_h^T) / 8
        tc_gemm<0, 1><<<dim3(Nn / BN, Nn / BM, NHEAD), 256>>>(
            q_, NHID, DKh, k_, NHID, DKh, S_, Nn, HS,
            nullptr, nullptr, 0, 0, 0.f, nullptr, nullptr, DKh, Nn, 0.125f);

        softmax_k<<<NHEAD * Nn, 256>>>(S_);

        // ctx_h = 0.5 * attn_h @ v_h + 0.5 * gv_h
        tc_gemm<0, 0><<<dim3(1, Nn / BM, NHEAD), 256>>>(
            S_, Nn, HS, v_, NHID, DKh, ctx_, NHID, DKh,
            nullptr, gv_, NHID, DKh, 0.5f, nullptr, nullptr, Nn, DKh, 0.5f);

        // pre = ctx @ Wo + bo + x
        tc_gemm<0, 0><<<gHid, 256>>>(ctx_, NHID, 0, Woi, NHID, 0, pre_, NHID, 0,
                                     bo + i * NHID, x_, NHID, 0, 1.f, nullptr, nullptr,
                                     NHID, NHID, 1.f);

        ln_prelu_k<<<Nn, 256>>>(pre_, x_, ln_g + i * NHID, ln_b + i * NHID, prelu_a + i);
    }

    cls_k<<<Nn, 128>>>(x_, w_cls, b_cls, out);
}

// round 6
// speedup vs baseline: 3.5378x; 2.0762x over previous
#include <cuda_runtime.h>
#include <cuda_bf16.h>
#include <math.h>
#include <stdint.h>

#define Nn 4096
#define Ee 4096
#define NHID 512
#define NHEAD 8
#define DKh 64
#define NLAYER 4
#define NCLASS 16
#define CAP 128

// ---------------- scratch ----------------
__device__ float g_x[Nn * NHID];
__device__ float g_q[Nn * NHID];
__device__ float g_k[Nn * NHID];
__device__ float g_v[Nn * NHID];
__device__ float g_w[Ee * NHID];
__device__ float g_gv[Nn * NHID];
__device__ float g_ctx[Nn * NHID];
__device__ float g_pre[Nn * NHID];
__device__ float g_DV[Nn];
__device__ float g_DEpart[32 * Ee];
__device__ float g_dv2[Nn];
__device__ float g_invDE[Ee];
__device__ int   g_rowIdx[Nn * CAP];
__device__ int   g_rowCnt[Nn];
__device__ int   g_colIdx[Ee * CAP];
__device__ int   g_colCnt[Ee];

// ---------------- degrees ----------------
__global__ void row_sums_k(const float* __restrict__ H) {
    int t = threadIdx.x;
    const float* row = H + (size_t)blockIdx.x * Ee;
    float s = 0.f;
    for (int e = t; e < Ee; e += 256) s += row[e];
    __shared__ float red[256];
    red[t] = s; __syncthreads();
    for (int w = 128; w > 0; w >>= 1) { if (t < w) red[t] += red[t + w]; __syncthreads(); }
    if (t == 0) g_DV[blockIdx.x] = red[0];
}

__global__ void col_part_k(const float* __restrict__ H) {
    int e = blockIdx.x * 256 + threadIdx.x;
    int r0 = blockIdx.y * 128;
    float s = 0.f;
    for (int n = r0; n < r0 + 128; n++) s += H[(size_t)n * Ee + e];
    g_DEpart[blockIdx.y * Ee + e] = s;
}

__global__ void finalize_deg_k() {
    int i = blockIdx.x * 256 + threadIdx.x;
    if (i < Nn) g_dv2[i] = (i == 0) ? 1.0f : rsqrtf(g_DV[i]);
    if (i < Ee) {
        float s = 0.f;
        for (int p = 0; p < 32; p++) s += g_DEpart[p * Ee + i];
        g_invDE[i] = 1.0f / s;
    }
}

// ---------------- CSR build (deterministic) ----------------
// Row lists: warp per row, ballot-compact in ascending e order.
__global__ void rowlist_k(const float* __restrict__ H) {
    int warp = threadIdx.x >> 5, lane = threadIdx.x & 31;
    int n = blockIdx.x * 8 + warp;
    const float* row = H + (size_t)n * Ee;
    int cnt = 0;
    for (int base = 0; base < Ee; base += 32) {
        float v = row[base + lane];
        unsigned mask = __ballot_sync(0xffffffffu, v != 0.f);
        int off = __popc(mask & ((1u << lane) - 1u));
        if (v != 0.f && cnt + off < CAP) g_rowIdx[n * CAP + cnt + off] = base + lane;
        cnt += __popc(mask);
    }
    if (lane == 0) g_rowCnt[n] = cnt < CAP ? cnt : CAP;
}

// Col lists: one thread per column e, ascending n (coalesced across e).
__global__ void collist_k(const float* __restrict__ H) {
    int e = blockIdx.x * 256 + threadIdx.x;
    int cnt = 0;
    for (int n = 0; n < Nn; n++) {
        if (H[(size_t)n * Ee + e] != 0.f) {
            if (cnt < CAP) g_colIdx[e * CAP + cnt] = n;
            cnt++;
        }
    }
    g_colCnt[e] = cnt < CAP ? cnt : CAP;
}

// ---------------- sparse gathers (replace dense H GEMMs) ----------------
// w[e,:] = invDE[e] * sum_{n in col(e)} dv2[n] * v[n,:]
__global__ void edge_gather_k(const float* __restrict__ v) {
    int e = blockIdx.x, t = threadIdx.x;   // 128 threads
    int cnt = g_colCnt[e];
    float inv = g_invDE[e];
    float4 acc = make_float4(0.f, 0.f, 0.f, 0.f);
    const int* lst = g_colIdx + e * CAP;
    for (int j = 0; j < cnt; j++) {
        int n = lst[j];
        float s = g_dv2[n];
        float4 x = *(const float4*)&v[(size_t)n * NHID + t * 4];
        acc.x += s * x.x; acc.y += s * x.y; acc.z += s * x.z; acc.w += s * x.w;
    }
    float4 r = make_float4(inv * acc.x, inv * acc.y, inv * acc.z, inv * acc.w);
    *(float4*)&g_w[(size_t)e * NHID + t * 4] = r;
}

// gv[n,:] = dv2[n] * sum_{e in row(n)} w[e,:]
__global__ void node_gather_k() {
    int n = blockIdx.x, t = threadIdx.x;   // 128 threads
    int cnt = g_rowCnt[n];
    float s = g_dv2[n];
    float4 acc = make_float4(0.f, 0.f, 0.f, 0.f);
    const int* lst = g_rowIdx + n * CAP;
    for (int j = 0; j < cnt; j++) {
        int e = lst[j];
        float4 x = *(const float4*)&g_w[(size_t)e * NHID + t * 4];
        acc.x += x.x; acc.y += x.y; acc.z += x.z; acc.w += x.w;
    }
    float4 r = make_float4(s * acc.x, s * acc.y, s * acc.z, s * acc.w);
    *(float4*)&g_gv[(size_t)n * NHID + t * 4] = r;
}

// ---------------- tf32 helpers ----------------
__device__ __forceinline__ float tf32_rna(float x) {
    float r;
    asm("cvt.rna.tf32.f32 %0, %1;" : "=f"(r) : "f"(x));
    return r;
}

__device__ __forceinline__ void mma_tf32(float c[4], uint32_t a0, uint32_t a1,
                                         uint32_t a2, uint32_t a3,
                                         uint32_t b0, uint32_t b1) {
    asm volatile(
        "mma.sync.aligned.m16n8k8.row.col.f32.tf32.tf32.f32 "
        "{%0,%1,%2,%3},{%4,%5,%6,%7},{%8,%9},{%0,%1,%2,%3};"
        : "+f"(c[0]), "+f"(c[1]), "+f"(c[2]), "+f"(c[3])
        : "r"(a0), "r"(a1), "r"(a2), "r"(a3), "r"(b0), "r"(b1));
}

// FMA-pipe exp for x <= 0 (avoids MUFU bottleneck). rel err ~1e-7.
__device__ __forceinline__ float fexp(float x) {
    float y = x * 1.44269504088896f;
    y = fmaxf(y, -126.f);
    float r = rintf(y);
    float f = y - r;
    float p = 1.5426461e-4f;                    // ln2^6/720
    p = fmaf(p, f, 1.3333558e-3f);              // ln2^5/120
    p = fmaf(p, f, 9.6181291e-3f);              // ln2^4/24
    p = fmaf(p, f, 5.5504109e-2f);              // ln2^3/6
    p = fmaf(p, f, 2.4022651e-1f);              // ln2^2/2
    p = fmaf(p, f, 6.9314718e-1f);              // ln2
    p = fmaf(p, f, 1.0f);
    float sc = __int_as_float(((int)r + 127) << 23);
    return p * sc;
}

// ---------------- dense split-tf32 GEMM (hidden projections) ----------------
#define BM 128
#define BN 128
#define BK 32

__global__ __launch_bounds__(256) void tc_gemm(
    const float* __restrict__ A, int lda,
    const float* __restrict__ B, int ldb,
    float* __restrict__ C, int ldc,
    const float* __restrict__ bias,
    const float* __restrict__ add, float addScale,
    int K) {
    __shared__ float As[BK][BM + 4];
    __shared__ float Bs[BK][BN + 4];

    int t = threadIdx.x;
    int lane = t & 31;
    int warp = t >> 5;
    int wm = (warp >> 2) * 64;
    int wn = (warp & 3) * 32;
    int m0 = blockIdx.y * BM;
    int n0 = blockIdx.x * BN;

    float acc[4][4][4];
#pragma unroll
    for (int i = 0; i < 4; i++)
#pragma unroll
        for (int j = 0; j < 4; j++)
#pragma unroll
            for (int r = 0; r < 4; r++) acc[i][j][r] = 0.f;

    for (int k0 = 0; k0 < K; k0 += BK) {
        {
            int row = t >> 3, kq = t & 7;
#pragma unroll
            for (int p = 0; p < 4; p++) {
                int m = row + p * 32;
                float4 a = *(const float4*)&A[(size_t)(m0 + m) * lda + k0 + kq * 4];
                As[kq * 4 + 0][m] = a.x;
                As[kq * 4 + 1][m] = a.y;
                As[kq * 4 + 2][m] = a.z;
                As[kq * 4 + 3][m] = a.w;
            }
            int kk = t >> 5, nq = t & 31;
#pragma unroll
            for (int p = 0; p < 4; p++) {
                int k = kk + p * 8;
                float4 b = *(const float4*)&B[(size_t)(k0 + k) * ldb + n0 + nq * 4];
                *(float4*)&Bs[k][nq * 4] = b;
            }
        }
        __syncthreads();

#pragma unroll
        for (int kk = 0; kk < 4; kk++) {
            int kb = kk * 8 + (lane & 3);
            uint32_t ahi[4][4], alo[4][4], bhi[4][2], blo[4][2];
#pragma unroll
            for (int mi = 0; mi < 4; mi++) {
                int r = wm + mi * 16 + (lane >> 2);
                float x0 = As[kb][r], x1 = As[kb][r + 8];
                float x2 = As[kb + 4][r], x3 = As[kb + 4][r + 8];
                float h0 = tf32_rna(x0), h1 = tf32_rna(x1), h2 = tf32_rna(x2), h3 = tf32_rna(x3);
                ahi[mi][0] = __float_as_uint(h0);
                ahi[mi][1] = __float_as_uint(h1);
                ahi[mi][2] = __float_as_uint(h2);
                ahi[mi][3] = __float_as_uint(h3);
                alo[mi][0] = __float_as_uint(tf32_rna(x0 - h0));
                alo[mi][1] = __float_as_uint(tf32_rna(x1 - h1));
                alo[mi][2] = __float_as_uint(tf32_rna(x2 - h2));
                alo[mi][3] = __float_as_uint(tf32_rna(x3 - h3));
            }
#pragma unroll
            for (int ni = 0; ni < 4; ni++) {
                int c = wn + ni * 8 + (lane >> 2);
                float y0 = Bs[kb][c], y1 = Bs[kb + 4][c];
                float g0 = tf32_rna(y0), g1 = tf32_rna(y1);
                bhi[ni][0] = __float_as_uint(g0);
                bhi[ni][1] = __float_as_uint(g1);
                blo[ni][0] = __float_as_uint(tf32_rna(y0 - g0));
                blo[ni][1] = __float_as_uint(tf32_rna(y1 - g1));
            }
#pragma unroll
            for (int mi = 0; mi < 4; mi++)
#pragma unroll
                for (int ni = 0; ni < 4; ni++) {
                    mma_tf32(acc[mi][ni], ahi[mi][0], ahi[mi][1], ahi[mi][2], ahi[mi][3],
                             bhi[ni][0], bhi[ni][1]);
                    mma_tf32(acc[mi][ni], ahi[mi][0], ahi[mi][1], ahi[mi][2], ahi[mi][3],
                             blo[ni][0], blo[ni][1]);
                    mma_tf32(acc[mi][ni], alo[mi][0], alo[mi][1], alo[mi][2], alo[mi][3],
                             bhi[ni][0], bhi[ni][1]);
                }
        }
        __syncthreads();
    }

#pragma unroll
    for (int mi = 0; mi < 4; mi++) {
        int r0 = m0 + wm + mi * 16 + (lane >> 2);
        int r1 = r0 + 8;
#pragma unroll
        for (int ni = 0; ni < 4; ni++) {
            int c0 = n0 + wn + ni * 8 + (lane & 3) * 2;
            int c1 = c0 + 1;
            float v00 = acc[mi][ni][0];
            float v01 = acc[mi][ni][1];
            float v10 = acc[mi][ni][2];
            float v11 = acc[mi][ni][3];
            if (bias) { v00 += bias[c0]; v01 += bias[c1]; v10 += bias[c0]; v11 += bias[c1]; }
            if (add) {
                v00 += addScale * add[(size_t)r0 * ldc + c0];
                v01 += addScale * add[(size_t)r0 * ldc + c1];
                v10 += addScale * add[(size_t)r1 * ldc + c0];
                v11 += addScale * add[(size_t)r1 * ldc + c1];
            }
            C[(size_t)r0 * ldc + c0] = v00;
            C[(size_t)r0 * ldc + c1] = v01;
            C[(size_t)r1 * ldc + c0] = v10;
            C[(size_t)r1 * ldc + c1] = v11;
        }
    }
}

// ---------------- fused flash attention ----------------
// Grid: (32 row-blocks, 8 heads). Block: 256 threads (8 warps x 16 rows).
// ctx[n, h*64+d] = 0.5 * softmax(Q_h K_h^T / 8) V_h + 0.5 * gv[n, h*64+d]
#define FBC 64
#define KLD 68
#define PLD 132

__global__ __launch_bounds__(256, 1) void flash_k(
    const float* __restrict__ Q, const float* __restrict__ Km,
    const float* __restrict__ Vm, const float* __restrict__ GV,
    float* __restrict__ CTX) {
    extern __shared__ float sm[];
    float* Ks = sm;                    // [64][KLD]  K^T of block
    float* Vs = sm + 64 * KLD;         // [64][KLD]  V of block
    float* Ps = sm + 2 * 64 * KLD;     // [64][PLD]  P (and Q staging)

    const int t = threadIdx.x, lane = t & 31, warp = t >> 5;
    const int h = blockIdx.y;
    const int r0 = blockIdx.x * 128;
    const int wr0 = warp * 16 + (lane >> 2);

    // ---- stage Q (scaled by 1/8) into Ps[d][row]
    {
        int row = t >> 1;
        int dbase = (t & 1) * 32;
        const float* src = Q + (size_t)(r0 + row) * NHID + h * DKh + dbase;
#pragma unroll
        for (int i = 0; i < 8; i++) {
            float4 a = *(const float4*)(src + i * 4);
            Ps[(dbase + i * 4 + 0) * PLD + row] = a.x;
            Ps[(dbase + i * 4 + 1) * PLD + row] = a.y;
            Ps[(dbase + i * 4 + 2) * PLD + row] = a.z;
            Ps[(dbase + i * 4 + 3) * PLD + row] = a.w;
        }
    }
    __syncthreads();

    uint32_t qh[8][4], ql[8][4];
#pragma unroll
    for (int kk = 0; kk < 8; kk++) {
        int kb = kk * 8 + (lane & 3);
        float x0 = Ps[kb * PLD + wr0] * 0.125f;
        float x1 = Ps[kb * PLD + wr0 + 8] * 0.125f;
        float x2 = Ps[(kb + 4) * PLD + wr0] * 0.125f;
        float x3 = Ps[(kb + 4) * PLD + wr0 + 8] * 0.125f;
        float h0 = tf32_rna(x0), h1 = tf32_rna(x1), h2 = tf32_rna(x2), h3 = tf32_rna(x3);
        qh[kk][0] = __float_as_uint(h0);
        qh[kk][1] = __float_as_uint(h1);
        qh[kk][2] = __float_as_uint(h2);
        qh[kk][3] = __float_as_uint(h3);
        ql[kk][0] = __float_as_uint(tf32_rna(x0 - h0));
        ql[kk][1] = __float_as_uint(tf32_rna(x1 - h1));
        ql[kk][2] = __float_as_uint(tf32_rna(x2 - h2));
        ql[kk][3] = __float_as_uint(tf32_rna(x3 - h3));
    }
    __syncthreads();

    float oacc[8][4];
#pragma unroll
    for (int ni = 0; ni < 8; ni++)
#pragma unroll
        for (int r = 0; r < 4; r++) oacc[ni][r] = 0.f;
    float m0 = -INFINITY, m1 = -INFINITY, l0 = 0.f, l1 = 0.f;

    for (int cb = 0; cb < Nn; cb += FBC) {
        // ---- load K (transposed) and V (direct)
        {
            int key = t & 63, dbase = (t >> 6) * 16;
            const float* kp = Km + (size_t)(cb + key) * NHID + h * DKh + dbase;
#pragma unroll
            for (int i = 0; i < 4; i++) {
                float4 a = *(const float4*)(kp + i * 4);
                Ks[(dbase + i * 4 + 0) * KLD + key] = a.x;
                Ks[(dbase + i * 4 + 1) * KLD + key] = a.y;
                Ks[(dbase + i * 4 + 2) * KLD + key] = a.z;
                Ks[(dbase + i * 4 + 3) * KLD + key] = a.w;
            }
            const float* vp = Vm + (size_t)(cb + key) * NHID + h * DKh + dbase;
#pragma unroll
            for (int i = 0; i < 4; i++) {
                float4 a = *(const float4*)(vp + i * 4);
                *(float4*)&Vs[key * KLD + dbase + i * 4] = a;
            }
        }
        __syncthreads();

        // ---- S = (Q/8) @ K^T   [16 x 64] per warp
        float sacc[8][4];
#pragma unroll
        for (int ni = 0; ni < 8; ni++)
#pragma unroll
            for (int r = 0; r < 4; r++) sacc[ni][r] = 0.f;
#pragma unroll
        for (int kk = 0; kk < 8; kk++) {
            int kb = kk * 8 + (lane & 3);
#pragma unroll
            for (int ni = 0; ni < 8; ni++) {
                int c = ni * 8 + (lane >> 2);
                float y0 = Ks[kb * KLD + c], y1 = Ks[(kb + 4) * KLD + c];
                float g0 = tf32_rna(y0), g1 = tf32_rna(y1);
                uint32_t b0 = __float_as_uint(g0), b1 = __float_as_uint(g1);
                uint32_t c0 = __float_as_uint(tf32_rna(y0 - g0));
                uint32_t c1 = __float_as_uint(tf32_rna(y1 - g1));
                mma_tf32(sacc[ni], qh[kk][0], qh[kk][1], qh[kk][2], qh[kk][3], b0, b1);
                mma_tf32(sacc[ni], qh[kk][0], qh[kk][1], qh[kk][2], qh[kk][3], c0, c1);
                mma_tf32(sacc[ni], ql[kk][0], ql[kk][1], ql[kk][2], ql[kk][3], b0, b1);
            }
        }

        // ---- online softmax (register-resident, FMA-pipe exp)
        float bm0 = -INFINITY, bm1 = -INFINITY;
#pragma unroll
        for (int ni = 0; ni < 8; ni++) {
            bm0 = fmaxf(bm0, fmaxf(sacc[ni][0], sacc[ni][1]));
            bm1 = fmaxf(bm1, fmaxf(sacc[ni][2], sacc[ni][3]));
        }
        bm0 = fmaxf(bm0, __shfl_xor_sync(0xffffffffu, bm0, 1));
        bm0 = fmaxf(bm0, __shfl_xor_sync(0xffffffffu, bm0, 2));
        bm1 = fmaxf(bm1, __shfl_xor_sync(0xffffffffu, bm1, 1));
        bm1 = fmaxf(bm1, __shfl_xor_sync(0xffffffffu, bm1, 2));
        float mn0 = fmaxf(m0, bm0), mn1 = fmaxf(m1, bm1);
        float cf0 = fexp(m0 - mn0), cf1 = fexp(m1 - mn1);
        float s0 = 0.f, s1 = 0.f;
#pragma unroll
        for (int ni = 0; ni < 8; ni++) {
            sacc[ni][0] = fexp(sacc[ni][0] - mn0);
            sacc[ni][1] = fexp(sacc[ni][1] - mn0);
            sacc[ni][2] = fexp(sacc[ni][2] - mn1);
            sacc[ni][3] = fexp(sacc[ni][3] - mn1);
            s0 += sacc[ni][0] + sacc[ni][1];
            s1 += sacc[ni][2] + sacc[ni][3];
        }
        s0 += __shfl_xor_sync(0xffffffffu, s0, 1);
        s0 += __shfl_xor_sync(0xffffffffu, s0, 2);
        s1 += __shfl_xor_sync(0xffffffffu, s1, 1);
        s1 += __shfl_xor_sync(0xffffffffu, s1, 2);
        l0 = l0 * cf0 + s0;
        l1 = l1 * cf1 + s1;
        m0 = mn0; m1 = mn1;
#pragma unroll
        for (int ni = 0; ni < 8; ni++) {
            oacc[ni][0] *= cf0; oacc[ni][1] *= cf0;
            oacc[ni][2] *= cf1; oacc[ni][3] *= cf1;
        }
        // ---- write P to Ps[key][row]
#pragma unroll
        for (int ni = 0; ni < 8; ni++) {
            int c = ni * 8 + (lane & 3) * 2;
            Ps[c * PLD + wr0] = sacc[ni][0];
            Ps[(c + 1) * PLD + wr0] = sacc[ni][1];
            Ps[c * PLD + wr0 + 8] = sacc[ni][2];
            Ps[(c + 1) * PLD + wr0 + 8] = sacc[ni][3];
        }
        __syncthreads();

        // ---- O += P @ V
#pragma unroll
        for (int kk = 0; kk < 8; kk++) {
            int kb = kk * 8 + (lane & 3);
            float x0 = Ps[kb * PLD + wr0];
            float x1 = Ps[kb * PLD + wr0 + 8];
            float x2 = Ps[(kb + 4) * PLD + wr0];
            float x3 = Ps[(kb + 4) * PLD + wr0 + 8];
            float h0 = tf32_rna(x0), h1 = tf32_rna(x1), h2 = tf32_rna(x2), h3 = tf32_rna(x3);
            uint32_t a0 = __float_as_uint(h0), a1 = __float_as_uint(h1);
            uint32_t a2 = __float_as_uint(h2), a3 = __float_as_uint(h3);
            uint32_t e0 = __float_as_uint(tf32_rna(x0 - h0));
            uint32_t e1 = __float_as_uint(tf32_rna(x1 - h1));
            uint32_t e2 = __float_as_uint(tf32_rna(x2 - h2));
            uint32_t e3 = __float_as_uint(tf32_rna(x3 - h3));
#pragma unroll
            for (int ni = 0; ni < 8; ni++) {
                int c = ni * 8 + (lane >> 2);
                float y0 = Vs[kb * KLD + c], y1 = Vs[(kb + 4) * KLD + c];
                float g0 = tf32_rna(y0), g1 = tf32_rna(y1);
                uint32_t b0 = __float_as_uint(g0), b1 = __float_as_uint(g1);
                uint32_t c0 = __float_as_uint(tf32_rna(y0 - g0));
                uint32_t c1 = __float_as_uint(tf32_rna(y1 - g1));
                mma_tf32(oacc[ni], a0, a1, a2, a3, b0, b1);
                mma_tf32(oacc[ni], a0, a1, a2, a3, c0, c1);
                mma_tf32(oacc[ni], e0, e1, e2, e3, b0, b1);
            }
        }
        __syncthreads();
    }

    // ---- epilogue: ctx = 0.5*O/l + 0.5*gv
    float inv0 = 0.5f / l0, inv1 = 0.5f / l1;
#pragma unroll
    for (int ni = 0; ni < 8; ni++) {
        int c = ni * 8 + (lane & 3) * 2;
        size_t o0 = (size_t)(r0 + wr0) * NHID + h * DKh + c;
        size_t o1 = (size_t)(r0 + wr0 + 8) * NHID + h * DKh + c;
        float2 gv0 = *(const float2*)&GV[o0];
        float2 gv1 = *(const float2*)&GV[o1];
        float2 w0, w1;
        w0.x = oacc[ni][0] * inv0 + 0.5f * gv0.x;
        w0.y = oacc[ni][1] * inv0 + 0.5f * gv0.y;
        w1.x = oacc[ni][2] * inv1 + 0.5f * gv1.x;
        w1.y = oacc[ni][3] * inv1 + 0.5f * gv1.y;
        *(float2*)&CTX[o0] = w0;
        *(float2*)&CTX[o1] = w1;
    }
}

// ---------------- layernorm + prelu ----------------
__global__ void ln_prelu_k(const float* __restrict__ in, float* __restrict__ out,
                           const float* __restrict__ g, const float* __restrict__ b,
                           const float* __restrict__ aptr) {
    int t = threadIdx.x;
    const float* row = in + (size_t)blockIdx.x * NHID;
    float x0 = row[t], x1 = row[t + 256];
    __shared__ float red[256];
    red[t] = x0 + x1; __syncthreads();
    for (int w = 128; w > 0; w >>= 1) { if (t < w) red[t] += red[t + w]; __syncthreads(); }
    float mu = red[0] * (1.0f / NHID);
    __syncthreads();
    float d0 = x0 - mu, d1 = x1 - mu;
    red[t] = d0 * d0 + d1 * d1; __syncthreads();
    for (int w = 128; w > 0; w >>= 1) { if (t < w) red[t] += red[t + w]; __syncthreads(); }
    float inv = rsqrtf(red[0] * (1.0f / NHID) + 1e-5f);
    float a = *aptr;
    float y0 = d0 * inv * g[t] + b[t];
    float y1 = d1 * inv * g[t + 256] + b[t + 256];
    float* orow = out + (size_t)blockIdx.x * NHID;
    orow[t] = (y0 >= 0.f) ? y0 : a * y0;
    orow[t + 256] = (y1 >= 0.f) ? y1 : a * y1;
}

// ---------------- classifier + log_softmax ----------------
__global__ void cls_k(const float* __restrict__ x, const float* __restrict__ w,
                      const float* __restrict__ bias, float* __restrict__ out) {
    __shared__ float xs[NHID];
    __shared__ float lg[NCLASS];
    int t = threadIdx.x;  // 128
    const float* row = x + (size_t)blockIdx.x * NHID;
    for (int i = t; i < NHID; i += 128) xs[i] = row[i];
    __syncthreads();
    if (t < NCLASS) {
        float s = bias[t];
        for (int k = 0; k < NHID; k++) s += xs[k] * w[k * NCLASS + t];
        lg[t] = s;
    }
    __syncthreads();
    if (t < NCLASS) {
        float mx = -INFINITY;
        for (int c = 0; c < NCLASS; c++) mx = fmaxf(mx, lg[c]);
        float sum = 0.f;
        for (int c = 0; c < NCLASS; c++) sum += __expf(lg[c] - mx);
        out[(size_t)blockIdx.x * NCLASS + t] = lg[t] - mx - logf(sum);
    }
}

// ---------------- host launcher ----------------
extern "C" void kernel_launch(void* const* d_in, const int* in_sizes, int n_in,
                              void* d_out, int out_size) {
    const float* X0     = (const float*)d_in[0];
    const float* Hm     = (const float*)d_in[1];
    const float* w_feat = (const float*)d_in[2];
    const float* b_feat = (const float*)d_in[3];
    const float* Wq     = (const float*)d_in[4];
    const float* bq     = (const float*)d_in[5];
    const float* Wk     = (const float*)d_in[6];
    const float* bk     = (const float*)d_in[7];
    const float* Wv     = (const float*)d_in[8];
    const float* bv     = (const float*)d_in[9];
    const float* Wo     = (const float*)d_in[10];
    const float* bo     = (const float*)d_in[11];
    const float* ln_g   = (const float*)d_in[12];
    const float* ln_b   = (const float*)d_in[13];
    const float* prelu_a= (const float*)d_in[14];
    const float* w_cls  = (const float*)d_in[15];
    const float* b_cls  = (const float*)d_in[16];
    float* out = (float*)d_out;

    float *x_, *q_, *k_, *v_, *gv_, *ctx_, *pre_;
    cudaGetSymbolAddress((void**)&x_, g_x);
    cudaGetSymbolAddress((void**)&q_, g_q);
    cudaGetSymbolAddress((void**)&k_, g_k);
    cudaGetSymbolAddress((void**)&v_, g_v);
    cudaGetSymbolAddress((void**)&gv_, g_gv);
    cudaGetSymbolAddress((void**)&ctx_, g_ctx);
    cudaGetSymbolAddress((void**)&pre_, g_pre);

    const int flashSmem = (2 * 64 * KLD + 64 * PLD) * 4;  // 68608 bytes
    cudaFuncSetAttribute(flash_k, cudaFuncAttributeMaxDynamicSharedMemorySize, flashSmem);

    // degrees + CSR
    row_sums_k<<<Nn, 256>>>(Hm);
    col_part_k<<<dim3(Ee / 256, 32), 256>>>(Hm);
    finalize_deg_k<<<Nn / 256, 256>>>();
    rowlist_k<<<Nn / 8, 256>>>(Hm);
    collist_k<<<Ee / 256, 256>>>(Hm);

    dim3 gHid(NHID / BN, Nn / BM);

    // x = X0 @ w_feat + b_feat
    tc_gemm<<<gHid, 256>>>(X0, NHID, w_feat, NHID, x_, NHID, b_feat, nullptr, 0.f, NHID);

    for (int i = 0; i < NLAYER; i++) {
        const float* Wqi = Wq + (size_t)i * NHID * NHID;
        const float* Wki = Wk + (size_t)i * NHID * NHID;
        const float* Wvi = Wv + (size_t)i * NHID * NHID;
        const float* Woi = Wo + (size_t)i * NHID * NHID;

        tc_gemm<<<gHid, 256>>>(x_, NHID, Wqi, NHID, q_, NHID, bq + i * NHID, nullptr, 0.f, NHID);
        tc_gemm<<<gHid, 256>>>(x_, NHID, Wki, NHID, k_, NHID, bk + i * NHID, nullptr, 0.f, NHID);
        tc_gemm<<<gHid, 256>>>(x_, NHID, Wvi, NHID, v_, NHID, bv + i * NHID, nullptr, 0.f, NHID);

        // sparse Laplacian apply: gv = dv2 * H (invDE (H^T (dv2 * v)))
        edge_gather_k<<<Ee, 128>>>(v_);
        node_gather_k<<<Nn, 128>>>();

        // fused attention + blend
        flash_k<<<dim3(32, 8), 256, flashSmem>>>(q_, k_, v_, gv_, ctx_);

        // pre = ctx @ Wo + bo + x
        tc_gemm<<<gHid, 256>>>(ctx_, NHID, Woi, NHID, pre_, NHID, bo + i * NHID, x_, 1.f, NHID);

        ln_prelu_k<<<Nn, 256>>>(pre_, x_, ln_g + i * NHID, ln_b + i * NHID, prelu_a + i);
    }

    cls_k<<<Nn, 128>>>(x_, w_cls, b_cls, out);
}

// round 7
// speedup vs baseline: 6.0346x; 1.7057x over previous
#include <cuda_runtime.h>
#include <cuda_bf16.h>
#include <math.h>
#include <stdint.h>

#define Nn 4096
#define Ee 4096
#define NHID 512
#define NHEAD 8
#define DKh 64
#define NLAYER 4
#define NCLASS 16
#define CAP 128

// ---------------- scratch ----------------
__device__ float g_x[Nn * NHID];
__device__ float g_q[Nn * NHID];
__device__ float g_k[Nn * NHID];
__device__ float g_v[Nn * NHID];
__device__ float g_w[Ee * NHID];
__device__ float g_gv[Nn * NHID];
__device__ float g_ctx[Nn * NHID];
__device__ float g_pre[Nn * NHID];
__device__ float g_DV[Nn];
__device__ float g_DEpart[32 * Ee];
__device__ float g_dv2[Nn];
__device__ float g_invDE[Ee];
__device__ int   g_rowIdx[Nn * CAP];
__device__ int   g_rowCnt[Nn];
__device__ int   g_colIdx[Ee * CAP];
__device__ int   g_colCnt[Ee];

// ---------------- degrees ----------------
__global__ void row_sums_k(const float* __restrict__ H) {
    int t = threadIdx.x;
    const float* row = H + (size_t)blockIdx.x * Ee;
    float s = 0.f;
    for (int e = t; e < Ee; e += 256) s += row[e];
    __shared__ float red[256];
    red[t] = s; __syncthreads();
    for (int w = 128; w > 0; w >>= 1) { if (t < w) red[t] += red[t + w]; __syncthreads(); }
    if (t == 0) g_DV[blockIdx.x] = red[0];
}

__global__ void col_part_k(const float* __restrict__ H) {
    int e = blockIdx.x * 256 + threadIdx.x;
    int r0 = blockIdx.y * 128;
    float s = 0.f;
    for (int n = r0; n < r0 + 128; n++) s += H[(size_t)n * Ee + e];
    g_DEpart[blockIdx.y * Ee + e] = s;
}

__global__ void finalize_deg_k() {
    int i = blockIdx.x * 256 + threadIdx.x;
    if (i < Nn) g_dv2[i] = (i == 0) ? 1.0f : rsqrtf(g_DV[i]);
    if (i < Ee) {
        float s = 0.f;
        for (int p = 0; p < 32; p++) s += g_DEpart[p * Ee + i];
        g_invDE[i] = 1.0f / s;
    }
}

// ---------------- CSR build (deterministic) ----------------
__global__ void rowlist_k(const float* __restrict__ H) {
    int warp = threadIdx.x >> 5, lane = threadIdx.x & 31;
    int n = blockIdx.x * 8 + warp;
    const float* row = H + (size_t)n * Ee;
    int cnt = 0;
    for (int base = 0; base < Ee; base += 32) {
        float v = row[base + lane];
        unsigned mask = __ballot_sync(0xffffffffu, v != 0.f);
        int off = __popc(mask & ((1u << lane) - 1u));
        if (v != 0.f && cnt + off < CAP) g_rowIdx[n * CAP + cnt + off] = base + lane;
        cnt += __popc(mask);
    }
    if (lane == 0) g_rowCnt[n] = cnt < CAP ? cnt : CAP;
}

__global__ void collist_k(const float* __restrict__ H) {
    int e = blockIdx.x * 256 + threadIdx.x;
    int cnt = 0;
    for (int n = 0; n < Nn; n++) {
        if (H[(size_t)n * Ee + e] != 0.f) {
            if (cnt < CAP) g_colIdx[e * CAP + cnt] = n;
            cnt++;
        }
    }
    g_colCnt[e] = cnt < CAP ? cnt : CAP;
}

// ---------------- sparse gathers ----------------
__global__ void edge_gather_k(const float* __restrict__ v) {
    int e = blockIdx.x, t = threadIdx.x;   // 128 threads
    int cnt = g_colCnt[e];
    float inv = g_invDE[e];
    float4 acc = make_float4(0.f, 0.f, 0.f, 0.f);
    const int* lst = g_colIdx + e * CAP;
    for (int j = 0; j < cnt; j++) {
        int n = lst[j];
        float s = g_dv2[n];
        float4 x = *(const float4*)&v[(size_t)n * NHID + t * 4];
        acc.x += s * x.x; acc.y += s * x.y; acc.z += s * x.z; acc.w += s * x.w;
    }
    float4 r = make_float4(inv * acc.x, inv * acc.y, inv * acc.z, inv * acc.w);
    *(float4*)&g_w[(size_t)e * NHID + t * 4] = r;
}

__global__ void node_gather_k() {
    int n = blockIdx.x, t = threadIdx.x;   // 128 threads
    int cnt = g_rowCnt[n];
    float s = g_dv2[n];
    float4 acc = make_float4(0.f, 0.f, 0.f, 0.f);
    const int* lst = g_rowIdx + n * CAP;
    for (int j = 0; j < cnt; j++) {
        int e = lst[j];
        float4 x = *(const float4*)&g_w[(size_t)e * NHID + t * 4];
        acc.x += x.x; acc.y += x.y; acc.z += x.z; acc.w += x.w;
    }
    float4 r = make_float4(s * acc.x, s * acc.y, s * acc.z, s * acc.w);
    *(float4*)&g_gv[(size_t)n * NHID + t * 4] = r;
}

// ---------------- bf16 split helpers ----------------
// word = {lo16: bf16(x0), hi16: bf16(x1)}; residual word likewise.
__device__ __forceinline__ void split2(float x0, float x1, uint32_t& hi, uint32_t& lo) {
    uint32_t h;
    asm("cvt.rn.bf16x2.f32 %0, %1, %2;" : "=r"(h) : "f"(x1), "f"(x0));
    float h0 = __uint_as_float(h << 16);
    float h1 = __uint_as_float(h & 0xffff0000u);
    asm("cvt.rn.bf16x2.f32 %0, %1, %2;" : "=r"(lo) : "f"(x1 - h1), "f"(x0 - h0));
    hi = h;
}

__device__ __forceinline__ void mma_bf16(float c[4], uint32_t a0, uint32_t a1,
                                         uint32_t a2, uint32_t a3,
                                         uint32_t b0, uint32_t b1) {
    asm volatile(
        "mma.sync.aligned.m16n8k16.row.col.f32.bf16.bf16.f32 "
        "{%0,%1,%2,%3},{%4,%5,%6,%7},{%8,%9},{%0,%1,%2,%3};"
        : "+f"(c[0]), "+f"(c[1]), "+f"(c[2]), "+f"(c[3])
        : "r"(a0), "r"(a1), "r"(a2), "r"(a3), "r"(b0), "r"(b1));
}

// FMA-pipe exp for x <= 0. rel err ~1e-7.
__device__ __forceinline__ float fexp(float x) {
    float y = x * 1.44269504088896f;
    y = fmaxf(y, -126.f);
    float r = rintf(y);
    float f = y - r;
    float p = 1.5426461e-4f;
    p = fmaf(p, f, 1.3333558e-3f);
    p = fmaf(p, f, 9.6181291e-3f);
    p = fmaf(p, f, 5.5504109e-2f);
    p = fmaf(p, f, 2.4022651e-1f);
    p = fmaf(p, f, 6.9314718e-1f);
    p = fmaf(p, f, 1.0f);
    float sc = __int_as_float(((int)r + 127) << 23);
    return p * sc;
}

// ---------------- dense split-bf16 GEMM (128x128x32 tile) ----------------
#define BM 128
#define BN 128
#define BK 32
#define LDg 136

__global__ __launch_bounds__(256) void tc_gemm(
    const float* __restrict__ A, int lda,
    const float* __restrict__ B, int ldb,
    float* __restrict__ C, int ldc,
    const float* __restrict__ bias,
    const float* __restrict__ add, float addScale,
    int K) {
    __shared__ uint32_t As_hi[16][LDg], As_lo[16][LDg];
    __shared__ uint32_t Bs_hi[16][LDg], Bs_lo[16][LDg];

    int t = threadIdx.x;
    int lane = t & 31;
    int warp = t >> 5;
    int lq = lane & 3;
    int lr = lane >> 2;
    int wm = (warp >> 2) * 64;
    int wn = (warp & 3) * 32;
    int m0 = blockIdx.y * BM;
    int n0 = blockIdx.x * BN;

    float acc[4][4][4];
#pragma unroll
    for (int i = 0; i < 4; i++)
#pragma unroll
        for (int j = 0; j < 4; j++)
#pragma unroll
            for (int r = 0; r < 4; r++) acc[i][j][r] = 0.f;

    for (int k0 = 0; k0 < K; k0 += BK) {
        // A tile: pairs along k (contiguous in row) -> As[pair][m]
        {
            int row = t >> 3, kq = t & 7;
#pragma unroll
            for (int p = 0; p < 4; p++) {
                int m = row + p * 32;
                float4 a = *(const float4*)&A[(size_t)(m0 + m) * lda + k0 + kq * 4];
                uint32_t h0, l0, h1, l1;
                split2(a.x, a.y, h0, l0);
                split2(a.z, a.w, h1, l1);
                As_hi[kq * 2 + 0][m] = h0; As_lo[kq * 2 + 0][m] = l0;
                As_hi[kq * 2 + 1][m] = h1; As_lo[kq * 2 + 1][m] = l1;
            }
        }
        // B tile: pairs along k (two rows) -> Bs[pair][n]
        {
#pragma unroll
            for (int p2 = 0; p2 < 2; p2++) {
                int tt = t + 256 * p2;
                int pr = tt >> 5, nq = tt & 31;
                float4 b0 = *(const float4*)&B[(size_t)(k0 + 2 * pr) * ldb + n0 + nq * 4];
                float4 b1 = *(const float4*)&B[(size_t)(k0 + 2 * pr + 1) * ldb + n0 + nq * 4];
                uint32_t h, l;
                split2(b0.x, b1.x, h, l); Bs_hi[pr][nq * 4 + 0] = h; Bs_lo[pr][nq * 4 + 0] = l;
                split2(b0.y, b1.y, h, l); Bs_hi[pr][nq * 4 + 1] = h; Bs_lo[pr][nq * 4 + 1] = l;
                split2(b0.z, b1.z, h, l); Bs_hi[pr][nq * 4 + 2] = h; Bs_lo[pr][nq * 4 + 2] = l;
                split2(b0.w, b1.w, h, l); Bs_hi[pr][nq * 4 + 3] = h; Bs_lo[pr][nq * 4 + 3] = l;
            }
        }
        __syncthreads();

#pragma unroll
        for (int kk = 0; kk < 2; kk++) {
            int p0 = kk * 8 + lq;
            uint32_t ah[4][4], al[4][4], bh[4][2], bl[4][2];
#pragma unroll
            for (int mi = 0; mi < 4; mi++) {
                int r = wm + mi * 16 + lr;
                ah[mi][0] = As_hi[p0][r];     al[mi][0] = As_lo[p0][r];
                ah[mi][1] = As_hi[p0][r + 8]; al[mi][1] = As_lo[p0][r + 8];
                ah[mi][2] = As_hi[p0 + 4][r];     al[mi][2] = As_lo[p0 + 4][r];
                ah[mi][3] = As_hi[p0 + 4][r + 8]; al[mi][3] = As_lo[p0 + 4][r + 8];
            }
#pragma unroll
            for (int ni = 0; ni < 4; ni++) {
                int c = wn + ni * 8 + lr;
                bh[ni][0] = Bs_hi[p0][c];     bl[ni][0] = Bs_lo[p0][c];
                bh[ni][1] = Bs_hi[p0 + 4][c]; bl[ni][1] = Bs_lo[p0 + 4][c];
            }
#pragma unroll
            for (int mi = 0; mi < 4; mi++)
#pragma unroll
                for (int ni = 0; ni < 4; ni++) {
                    mma_bf16(acc[mi][ni], ah[mi][0], ah[mi][1], ah[mi][2], ah[mi][3],
                             bh[ni][0], bh[ni][1]);
                    mma_bf16(acc[mi][ni], ah[mi][0], ah[mi][1], ah[mi][2], ah[mi][3],
                             bl[ni][0], bl[ni][1]);
                    mma_bf16(acc[mi][ni], al[mi][0], al[mi][1], al[mi][2], al[mi][3],
                             bh[ni][0], bh[ni][1]);
                }
        }
        __syncthreads();
    }

#pragma unroll
    for (int mi = 0; mi < 4; mi++) {
        int r0 = m0 + wm + mi * 16 + lr;
        int r1 = r0 + 8;
#pragma unroll
        for (int ni = 0; ni < 4; ni++) {
            int c0 = n0 + wn + ni * 8 + lq * 2;
            int c1 = c0 + 1;
            float v00 = acc[mi][ni][0];
            float v01 = acc[mi][ni][1];
            float v10 = acc[mi][ni][2];
            float v11 = acc[mi][ni][3];
            if (bias) { v00 += bias[c0]; v01 += bias[c1]; v10 += bias[c0]; v11 += bias[c1]; }
            if (add) {
                v00 += addScale * add[(size_t)r0 * ldc + c0];
                v01 += addScale * add[(size_t)r0 * ldc + c1];
                v10 += addScale * add[(size_t)r1 * ldc + c0];
                v11 += addScale * add[(size_t)r1 * ldc + c1];
            }
            C[(size_t)r0 * ldc + c0] = v00;
            C[(size_t)r0 * ldc + c1] = v01;
            C[(size_t)r1 * ldc + c0] = v10;
            C[(size_t)r1 * ldc + c1] = v11;
        }
    }
}

// ---------------- fused flash attention (split-bf16) ----------------
// Grid: (32 row-blocks, 8 heads). Block: 256 threads (8 warps x 16 rows).
#define FBC 64
#define KLD 72   // stride (words) for K/V pair arrays [32][72]
#define PLD 136  // stride (words) for P pair arrays  [32][136]

// dynamic smem word offsets
#define OFF_KHI 0
#define OFF_KLO (OFF_KHI + 32 * KLD)
#define OFF_VHI (OFF_KLO + 32 * KLD)
#define OFF_VLO (OFF_VHI + 32 * KLD)
#define OFF_PHI (OFF_VLO + 32 * KLD)
#define OFF_PLO (OFF_PHI + 32 * PLD)
#define FLASH_WORDS (OFF_PLO + 32 * PLD)

__global__ __launch_bounds__(256, 1) void flash_k(
    const float* __restrict__ Q, const float* __restrict__ Km,
    const float* __restrict__ Vm, const float* __restrict__ GV,
    float* __restrict__ CTX) {
    extern __shared__ uint32_t sm[];
    uint32_t* Khi = sm + OFF_KHI;
    uint32_t* Klo = sm + OFF_KLO;
    uint32_t* Vhi = sm + OFF_VHI;
    uint32_t* Vlo = sm + OFF_VLO;
    uint32_t* Phi = sm + OFF_PHI;
    uint32_t* Plo = sm + OFF_PLO;
    float* Qst = (float*)(sm + OFF_PHI);   // [64][PLD] floats, overlays P region

    const int t = threadIdx.x, lane = t & 31, warp = t >> 5;
    const int lq = lane & 3, lr = lane >> 2;
    const int h = blockIdx.y;
    const int r0 = blockIdx.x * 128;
    const int wr0 = warp * 16 + lr;

    // ---- stage Q into Qst[d][row]
    {
        int row = t >> 1;
        int dbase = (t & 1) * 32;
        const float* src = Q + (size_t)(r0 + row) * NHID + h * DKh + dbase;
#pragma unroll
        for (int i = 0; i < 8; i++) {
            float4 a = *(const float4*)(src + i * 4);
            Qst[(dbase + i * 4 + 0) * PLD + row] = a.x;
            Qst[(dbase + i * 4 + 1) * PLD + row] = a.y;
            Qst[(dbase + i * 4 + 2) * PLD + row] = a.z;
            Qst[(dbase + i * 4 + 3) * PLD + row] = a.w;
        }
    }
    __syncthreads();

    // ---- build Q fragments (scaled by 1/8), bf16 hi/lo
    uint32_t qh[4][4], ql[4][4];
#pragma unroll
    for (int s = 0; s < 4; s++) {
        int pa = s * 8 + lq;
#pragma unroll
        for (int half = 0; half < 2; half++) {
            int p = pa + half * 4;
            float x0 = Qst[(2 * p + 0) * PLD + wr0] * 0.125f;
            float x1 = Qst[(2 * p + 1) * PLD + wr0] * 0.125f;
            float y0 = Qst[(2 * p + 0) * PLD + wr0 + 8] * 0.125f;
            float y1 = Qst[(2 * p + 1) * PLD + wr0 + 8] * 0.125f;
            split2(x0, x1, qh[s][half * 2 + 0], ql[s][half * 2 + 0]);
            split2(y0, y1, qh[s][half * 2 + 1], ql[s][half * 2 + 1]);
        }
    }
    __syncthreads();

    float oacc[8][4];
#pragma unroll
    for (int ni = 0; ni < 8; ni++)
#pragma unroll
        for (int r = 0; r < 4; r++) oacc[ni][r] = 0.f;
    float m0 = -INFINITY, m1 = -INFINITY, l0 = 0.f, l1 = 0.f;

    for (int cb = 0; cb < Nn; cb += FBC) {
        // ---- load K: pairs along d -> Khi[d/2][key]
        {
            int key = t & 63, dbase = (t >> 6) * 16;
            const float* kp = Km + (size_t)(cb + key) * NHID + h * DKh + dbase;
#pragma unroll
            for (int i = 0; i < 4; i++) {
                float4 a = *(const float4*)(kp + i * 4);
                int p = (dbase + i * 4) >> 1;
                uint32_t h0, lo0, h1, lo1;
                split2(a.x, a.y, h0, lo0);
                split2(a.z, a.w, h1, lo1);
                Khi[(p + 0) * KLD + key] = h0; Klo[(p + 0) * KLD + key] = lo0;
                Khi[(p + 1) * KLD + key] = h1; Klo[(p + 1) * KLD + key] = lo1;
            }
        }
        // ---- load V: pairs along key -> Vhi[key/2][d]
        {
#pragma unroll
            for (int p2 = 0; p2 < 2; p2++) {
                int tt = t + 256 * p2;
                int kp = tt >> 4, dg = tt & 15;
                const float* v0p = Vm + (size_t)(cb + 2 * kp) * NHID + h * DKh + dg * 4;
                const float* v1p = v0p + NHID;
                float4 v0 = *(const float4*)v0p;
                float4 v1 = *(const float4*)v1p;
                uint32_t hh, ll;
                split2(v0.x, v1.x, hh, ll); Vhi[kp * KLD + dg * 4 + 0] = hh; Vlo[kp * KLD + dg * 4 + 0] = ll;
                split2(v0.y, v1.y, hh, ll); Vhi[kp * KLD + dg * 4 + 1] = hh; Vlo[kp * KLD + dg * 4 + 1] = ll;
                split2(v0.z, v1.z, hh, ll); Vhi[kp * KLD + dg * 4 + 2] = hh; Vlo[kp * KLD + dg * 4 + 2] = ll;
                split2(v0.w, v1.w, hh, ll); Vhi[kp * KLD + dg * 4 + 3] = hh; Vlo[kp * KLD + dg * 4 + 3] = ll;
            }
        }
        __syncthreads();

        // ---- S = (Q/8) @ K^T
        float sacc[8][4];
#pragma unroll
        for (int ni = 0; ni < 8; ni++)
#pragma unroll
            for (int r = 0; r < 4; r++) sacc[ni][r] = 0.f;
#pragma unroll
        for (int s = 0; s < 4; s++) {
            int p0 = s * 8 + lq;
#pragma unroll
            for (int ni = 0; ni < 8; ni++) {
                int c = ni * 8 + lr;
                uint32_t b0 = Khi[p0 * KLD + c], b1 = Khi[(p0 + 4) * KLD + c];
                uint32_t c0 = Klo[p0 * KLD + c], c1 = Klo[(p0 + 4) * KLD + c];
                mma_bf16(sacc[ni], qh[s][0], qh[s][1], qh[s][2], qh[s][3], b0, b1);
                mma_bf16(sacc[ni], qh[s][0], qh[s][1], qh[s][2], qh[s][3], c0, c1);
                mma_bf16(sacc[ni], ql[s][0], ql[s][1], ql[s][2], ql[s][3], b0, b1);
            }
        }

        // ---- online softmax
        float bm0 = -INFINITY, bm1 = -INFINITY;
#pragma unroll
        for (int ni = 0; ni < 8; ni++) {
            bm0 = fmaxf(bm0, fmaxf(sacc[ni][0], sacc[ni][1]));
            bm1 = fmaxf(bm1, fmaxf(sacc[ni][2], sacc[ni][3]));
        }
        bm0 = fmaxf(bm0, __shfl_xor_sync(0xffffffffu, bm0, 1));
        bm0 = fmaxf(bm0, __shfl_xor_sync(0xffffffffu, bm0, 2));
        bm1 = fmaxf(bm1, __shfl_xor_sync(0xffffffffu, bm1, 1));
        bm1 = fmaxf(bm1, __shfl_xor_sync(0xffffffffu, bm1, 2));
        float mn0 = fmaxf(m0, bm0), mn1 = fmaxf(m1, bm1);
        float cf0 = fexp(m0 - mn0), cf1 = fexp(m1 - mn1);
        float s0 = 0.f, s1 = 0.f;
#pragma unroll
        for (int ni = 0; ni < 8; ni++) {
            sacc[ni][0] = fexp(sacc[ni][0] - mn0);
            sacc[ni][1] = fexp(sacc[ni][1] - mn0);
            sacc[ni][2] = fexp(sacc[ni][2] - mn1);
            sacc[ni][3] = fexp(sacc[ni][3] - mn1);
            s0 += sacc[ni][0] + sacc[ni][1];
            s1 += sacc[ni][2] + sacc[ni][3];
        }
        s0 += __shfl_xor_sync(0xffffffffu, s0, 1);
        s0 += __shfl_xor_sync(0xffffffffu, s0, 2);
        s1 += __shfl_xor_sync(0xffffffffu, s1, 1);
        s1 += __shfl_xor_sync(0xffffffffu, s1, 2);
        l0 = l0 * cf0 + s0;
        l1 = l1 * cf1 + s1;
        m0 = mn0; m1 = mn1;
#pragma unroll
        for (int ni = 0; ni < 8; ni++) {
            oacc[ni][0] *= cf0; oacc[ni][1] *= cf0;
            oacc[ni][2] *= cf1; oacc[ni][3] *= cf1;
        }
        // ---- write P (bf16 hi/lo pairs along key) to Phi[pair][row]
#pragma unroll
        for (int ni = 0; ni < 8; ni++) {
            int pr = ni * 4 + lq;
            uint32_t hh, ll;
            split2(sacc[ni][0], sacc[ni][1], hh, ll);
            Phi[pr * PLD + wr0] = hh; Plo[pr * PLD + wr0] = ll;
            split2(sacc[ni][2], sacc[ni][3], hh, ll);
            Phi[pr * PLD + wr0 + 8] = hh; Plo[pr * PLD + wr0 + 8] = ll;
        }
        __syncthreads();

        // ---- O += P @ V
#pragma unroll
        for (int s = 0; s < 4; s++) {
            int p0 = s * 8 + lq;
            uint32_t a0 = Phi[p0 * PLD + wr0];
            uint32_t a1 = Phi[p0 * PLD + wr0 + 8];
            uint32_t a2 = Phi[(p0 + 4) * PLD + wr0];
            uint32_t a3 = Phi[(p0 + 4) * PLD + wr0 + 8];
            uint32_t e0 = Plo[p0 * PLD + wr0];
            uint32_t e1 = Plo[p0 * PLD + wr0 + 8];
            uint32_t e2 = Plo[(p0 + 4) * PLD + wr0];
            uint32_t e3 = Plo[(p0 + 4) * PLD + wr0 + 8];
#pragma unroll
            for (int ni = 0; ni < 8; ni++) {
                int c = ni * 8 + lr;
                uint32_t b0 = Vhi[p0 * KLD + c], b1 = Vhi[(p0 + 4) * KLD + c];
                uint32_t c0 = Vlo[p0 * KLD + c], c1 = Vlo[(p0 + 4) * KLD + c];
                mma_bf16(oacc[ni], a0, a1, a2, a3, b0, b1);
                mma_bf16(oacc[ni], a0, a1, a2, a3, c0, c1);
                mma_bf16(oacc[ni], e0, e1, e2, e3, b0, b1);
            }
        }
        __syncthreads();
    }

    // ---- epilogue: ctx = 0.5*O/l + 0.5*gv
    float inv0 = 0.5f / l0, inv1 = 0.5f / l1;
#pragma unroll
    for (int ni = 0; ni < 8; ni++) {
        int c = ni * 8 + lq * 2;
        size_t o0 = (size_t)(r0 + wr0) * NHID + h * DKh + c;
        size_t o1 = (size_t)(r0 + wr0 + 8) * NHID + h * DKh + c;
        float2 gv0 = *(const float2*)&GV[o0];
        float2 gv1 = *(const float2*)&GV[o1];
        float2 w0, w1;
        w0.x = oacc[ni][0] * inv0 + 0.5f * gv0.x;
        w0.y = oacc[ni][1] * inv0 + 0.5f * gv0.y;
        w1.x = oacc[ni][2] * inv1 + 0.5f * gv1.x;
        w1.y = oacc[ni][3] * inv1 + 0.5f * gv1.y;
        *(float2*)&CTX[o0] = w0;
        *(float2*)&CTX[o1] = w1;
    }
}

// ---------------- layernorm + prelu ----------------
__global__ void ln_prelu_k(const float* __restrict__ in, float* __restrict__ out,
                           const float* __restrict__ g, const float* __restrict__ b,
                           const float* __restrict__ aptr) {
    int t = threadIdx.x;
    const float* row = in + (size_t)blockIdx.x * NHID;
    float x0 = row[t], x1 = row[t + 256];
    __shared__ float red[256];
    red[t] = x0 + x1; __syncthreads();
    for (int w = 128; w > 0; w >>= 1) { if (t < w) red[t] += red[t + w]; __syncthreads(); }
    float mu = red[0] * (1.0f / NHID);
    __syncthreads();
    float d0 = x0 - mu, d1 = x1 - mu;
    red[t] = d0 * d0 + d1 * d1; __syncthreads();
    for (int w = 128; w > 0; w >>= 1) { if (t < w) red[t] += red[t + w]; __syncthreads(); }
    float inv = rsqrtf(red[0] * (1.0f / NHID) + 1e-5f);
    float a = *aptr;
    float y0 = d0 * inv * g[t] + b[t];
    float y1 = d1 * inv * g[t + 256] + b[t + 256];
    float* orow = out + (size_t)blockIdx.x * NHID;
    orow[t] = (y0 >= 0.f) ? y0 : a * y0;
    orow[t + 256] = (y1 >= 0.f) ? y1 : a * y1;
}

// ---------------- classifier + log_softmax ----------------
__global__ void cls_k(const float* __restrict__ x, const float* __restrict__ w,
                      const float* __restrict__ bias, float* __restrict__ out) {
    __shared__ float xs[NHID];
    __shared__ float lg[NCLASS];
    int t = threadIdx.x;  // 128
    const float* row = x + (size_t)blockIdx.x * NHID;
    for (int i = t; i < NHID; i += 128) xs[i] = row[i];
    __syncthreads();
    if (t < NCLASS) {
        float s = bias[t];
        for (int k = 0; k < NHID; k++) s += xs[k] * w[k * NCLASS + t];
        lg[t] = s;
    }
    __syncthreads();
    if (t < NCLASS) {
        float mx = -INFINITY;
        for (int c = 0; c < NCLASS; c++) mx = fmaxf(mx, lg[c]);
        float sum = 0.f;
        for (int c = 0; c < NCLASS; c++) sum += __expf(lg[c] - mx);
        out[(size_t)blockIdx.x * NCLASS + t] = lg[t] - mx - logf(sum);
    }
}

// ---------------- host launcher ----------------
extern "C" void kernel_launch(void* const* d_in, const int* in_sizes, int n_in,
                              void* d_out, int out_size) {
    const float* X0     = (const float*)d_in[0];
    const float* Hm     = (const float*)d_in[1];
    const float* w_feat = (const float*)d_in[2];
    const float* b_feat = (const float*)d_in[3];
    const float* Wq     = (const float*)d_in[4];
    const float* bq     = (const float*)d_in[5];
    const float* Wk     = (const float*)d_in[6];
    const float* bk     = (const float*)d_in[7];
    const float* Wv     = (const float*)d_in[8];
    const float* bv     = (const float*)d_in[9];
    const float* Wo     = (const float*)d_in[10];
    const float* bo     = (const float*)d_in[11];
    const float* ln_g   = (const float*)d_in[12];
    const float* ln_b   = (const float*)d_in[13];
    const float* prelu_a= (const float*)d_in[14];
    const float* w_cls  = (const float*)d_in[15];
    const float* b_cls  = (const float*)d_in[16];
    float* out = (float*)d_out;

    float *x_, *q_, *k_, *v_, *gv_, *ctx_, *pre_;
    cudaGetSymbolAddress((void**)&x_, g_x);
    cudaGetSymbolAddress((void**)&q_, g_q);
    cudaGetSymbolAddress((void**)&k_, g_k);
    cudaGetSymbolAddress((void**)&v_, g_v);
    cudaGetSymbolAddress((void**)&gv_, g_gv);
    cudaGetSymbolAddress((void**)&ctx_, g_ctx);
    cudaGetSymbolAddress((void**)&pre_, g_pre);

    const int flashSmem = FLASH_WORDS * 4;
    cudaFuncSetAttribute(flash_k, cudaFuncAttributeMaxDynamicSharedMemorySize, flashSmem);

    row_sums_k<<<Nn, 256>>>(Hm);
    col_part_k<<<dim3(Ee / 256, 32), 256>>>(Hm);
    finalize_deg_k<<<Nn / 256, 256>>>();
    rowlist_k<<<Nn / 8, 256>>>(Hm);
    collist_k<<<Ee / 256, 256>>>(Hm);

    dim3 gHid(NHID / BN, Nn / BM);

    tc_gemm<<<gHid, 256>>>(X0, NHID, w_feat, NHID, x_, NHID, b_feat, nullptr, 0.f, NHID);

    for (int i = 0; i < NLAYER; i++) {
        const float* Wqi = Wq + (size_t)i * NHID * NHID;
        const float* Wki = Wk + (size_t)i * NHID * NHID;
        const float* Wvi = Wv + (size_t)i * NHID * NHID;
        const float* Woi = Wo + (size_t)i * NHID * NHID;

        tc_gemm<<<gHid, 256>>>(x_, NHID, Wqi, NHID, q_, NHID, bq + i * NHID, nullptr, 0.f, NHID);
        tc_gemm<<<gHid, 256>>>(x_, NHID, Wki, NHID, k_, NHID, bk + i * NHID, nullptr, 0.f, NHID);
        tc_gemm<<<gHid, 256>>>(x_, NHID, Wvi, NHID, v_, NHID, bv + i * NHID, nullptr, 0.f, NHID);

        edge_gather_k<<<Ee, 128>>>(v_);
        node_gather_k<<<Nn, 128>>>();

        flash_k<<<dim3(32, 8), 256, flashSmem>>>(q_, k_, v_, gv_, ctx_);

        tc_gemm<<<gHid, 256>>>(ctx_, NHID, Woi, NHID, pre_, NHID, bo + i * NHID, x_, 1.f, NHID);

        ln_prelu_k<<<Nn, 256>>>(pre_, x_, ln_g + i * NHID, ln_b + i * NHID, prelu_a + i);
    }

    cls_k<<<Nn, 128>>>(x_, w_cls, b_cls, out);
}

// round 8
// speedup vs baseline: 6.7830x; 1.1240x over previous
#include <cuda_runtime.h>
#include <cuda_bf16.h>
#include <math.h>
#include <stdint.h>

#define Nn 4096
#define Ee 4096
#define NHID 512
#define NHEAD 8
#define DKh 64
#define NLAYER 4
#define NCLASS 16
#define CAP 128

// ---------------- scratch ----------------
__device__ float g_x[Nn * NHID];
__device__ float g_q[Nn * NHID];
__device__ float g_k[Nn * NHID];
__device__ float g_v[Nn * NHID];
__device__ float g_w[Ee * NHID];
__device__ float g_gv[Nn * NHID];
__device__ float g_ctx[Nn * NHID];
__device__ float g_pre[Nn * NHID];
__device__ float g_DV[Nn];
__device__ float g_DEpart[32 * Ee];
__device__ float g_dv2[Nn];
__device__ float g_invDE[Ee];
__device__ int   g_rowIdx[Nn * CAP];
__device__ int   g_rowCnt[Nn];
__device__ int   g_colIdx[Ee * CAP];
__device__ int   g_colCnt[Ee];

// ---------------- degrees ----------------
__global__ void row_sums_k(const float* __restrict__ H) {
    int t = threadIdx.x;
    const float* row = H + (size_t)blockIdx.x * Ee;
    float s = 0.f;
    for (int e = t; e < Ee; e += 256) s += row[e];
    __shared__ float red[256];
    red[t] = s; __syncthreads();
    for (int w = 128; w > 0; w >>= 1) { if (t < w) red[t] += red[t + w]; __syncthreads(); }
    if (t == 0) g_DV[blockIdx.x] = red[0];
}

__global__ void col_part_k(const float* __restrict__ H) {
    int e = blockIdx.x * 256 + threadIdx.x;
    int r0 = blockIdx.y * 128;
    float s = 0.f;
    for (int n = r0; n < r0 + 128; n++) s += H[(size_t)n * Ee + e];
    g_DEpart[blockIdx.y * Ee + e] = s;
}

__global__ void finalize_deg_k() {
    int i = blockIdx.x * 256 + threadIdx.x;
    if (i < Nn) g_dv2[i] = (i == 0) ? 1.0f : rsqrtf(g_DV[i]);
    if (i < Ee) {
        float s = 0.f;
        for (int p = 0; p < 32; p++) s += g_DEpart[p * Ee + i];
        g_invDE[i] = 1.0f / s;
    }
}

// ---------------- CSR build (deterministic) ----------------
__global__ void rowlist_k(const float* __restrict__ H) {
    int warp = threadIdx.x >> 5, lane = threadIdx.x & 31;
    int n = blockIdx.x * 8 + warp;
    const float* row = H + (size_t)n * Ee;
    int cnt = 0;
    for (int base = 0; base < Ee; base += 32) {
        float v = row[base + lane];
        unsigned mask = __ballot_sync(0xffffffffu, v != 0.f);
        int off = __popc(mask & ((1u << lane) - 1u));
        if (v != 0.f && cnt + off < CAP) g_rowIdx[n * CAP + cnt + off] = base + lane;
        cnt += __popc(mask);
    }
    if (lane == 0) g_rowCnt[n] = cnt < CAP ? cnt : CAP;
}

__global__ void collist_k(const float* __restrict__ H) {
    int e = blockIdx.x * 256 + threadIdx.x;
    int cnt = 0;
    for (int n = 0; n < Nn; n++) {
        if (H[(size_t)n * Ee + e] != 0.f) {
            if (cnt < CAP) g_colIdx[e * CAP + cnt] = n;
            cnt++;
        }
    }
    g_colCnt[e] = cnt < CAP ? cnt : CAP;
}

// ---------------- sparse gathers ----------------
__global__ void edge_gather_k(const float* __restrict__ v) {
    int e = blockIdx.x, t = threadIdx.x;   // 128 threads
    int cnt = g_colCnt[e];
    float inv = g_invDE[e];
    float4 acc = make_float4(0.f, 0.f, 0.f, 0.f);
    const int* lst = g_colIdx + e * CAP;
    for (int j = 0; j < cnt; j++) {
        int n = lst[j];
        float s = g_dv2[n];
        float4 x = *(const float4*)&v[(size_t)n * NHID + t * 4];
        acc.x += s * x.x; acc.y += s * x.y; acc.z += s * x.z; acc.w += s * x.w;
    }
    float4 r = make_float4(inv * acc.x, inv * acc.y, inv * acc.z, inv * acc.w);
    *(float4*)&g_w[(size_t)e * NHID + t * 4] = r;
}

__global__ void node_gather_k() {
    int n = blockIdx.x, t = threadIdx.x;   // 128 threads
    int cnt = g_rowCnt[n];
    float s = g_dv2[n];
    float4 acc = make_float4(0.f, 0.f, 0.f, 0.f);
    const int* lst = g_rowIdx + n * CAP;
    for (int j = 0; j < cnt; j++) {
        int e = lst[j];
        float4 x = *(const float4*)&g_w[(size_t)e * NHID + t * 4];
        acc.x += x.x; acc.y += x.y; acc.z += x.z; acc.w += x.w;
    }
    float4 r = make_float4(s * acc.x, s * acc.y, s * acc.z, s * acc.w);
    *(float4*)&g_gv[(size_t)n * NHID + t * 4] = r;
}

// ---------------- bf16 split helpers ----------------
__device__ __forceinline__ void split2(float x0, float x1, uint32_t& hi, uint32_t& lo) {
    uint32_t h;
    asm("cvt.rn.bf16x2.f32 %0, %1, %2;" : "=r"(h) : "f"(x1), "f"(x0));
    float h0 = __uint_as_float(h << 16);
    float h1 = __uint_as_float(h & 0xffff0000u);
    asm("cvt.rn.bf16x2.f32 %0, %1, %2;" : "=r"(lo) : "f"(x1 - h1), "f"(x0 - h0));
    hi = h;
}

__device__ __forceinline__ void mma_bf16(float c[4], uint32_t a0, uint32_t a1,
                                         uint32_t a2, uint32_t a3,
                                         uint32_t b0, uint32_t b1) {
    asm volatile(
        "mma.sync.aligned.m16n8k16.row.col.f32.bf16.bf16.f32 "
        "{%0,%1,%2,%3},{%4,%5,%6,%7},{%8,%9},{%0,%1,%2,%3};"
        : "+f"(c[0]), "+f"(c[1]), "+f"(c[2]), "+f"(c[3])
        : "r"(a0), "r"(a1), "r"(a2), "r"(a3), "r"(b0), "r"(b1));
}

// FMA-pipe exp for x <= 0. rel err ~1e-7.
__device__ __forceinline__ float fexp(float x) {
    float y = x * 1.44269504088896f;
    y = fmaxf(y, -126.f);
    float r = rintf(y);
    float f = y - r;
    float p = 1.5426461e-4f;
    p = fmaf(p, f, 1.3333558e-3f);
    p = fmaf(p, f, 9.6181291e-3f);
    p = fmaf(p, f, 5.5504109e-2f);
    p = fmaf(p, f, 2.4022651e-1f);
    p = fmaf(p, f, 6.9314718e-1f);
    p = fmaf(p, f, 1.0f);
    float sc = __int_as_float(((int)r + 127) << 23);
    return p * sc;
}

// ---------------- dense split-bf16 GEMM (128x128x32 tile) ----------------
#define BM 128
#define BN 128
#define BK 32
#define LDg 136

__device__ __forceinline__ void gemm_body(
    const float* __restrict__ A, int lda,
    const float* __restrict__ B, int ldb,
    float* __restrict__ C, int ldc,
    const float* __restrict__ bias,
    const float* __restrict__ add, float addScale,
    int K, int m0, int n0,
    uint32_t (*As_hi)[LDg], uint32_t (*As_lo)[LDg],
    uint32_t (*Bs_hi)[LDg], uint32_t (*Bs_lo)[LDg]) {
    int t = threadIdx.x;
    int lane = t & 31;
    int warp = t >> 5;
    int lq = lane & 3;
    int lr = lane >> 2;
    int wm = (warp >> 2) * 64;
    int wn = (warp & 3) * 32;

    float acc[4][4][4];
#pragma unroll
    for (int i = 0; i < 4; i++)
#pragma unroll
        for (int j = 0; j < 4; j++)
#pragma unroll
            for (int r = 0; r < 4; r++) acc[i][j][r] = 0.f;

    for (int k0 = 0; k0 < K; k0 += BK) {
        {
            int row = t >> 3, kq = t & 7;
#pragma unroll
            for (int p = 0; p < 4; p++) {
                int m = row + p * 32;
                float4 a = *(const float4*)&A[(size_t)(m0 + m) * lda + k0 + kq * 4];
                uint32_t h0, l0, h1, l1;
                split2(a.x, a.y, h0, l0);
                split2(a.z, a.w, h1, l1);
                As_hi[kq * 2 + 0][m] = h0; As_lo[kq * 2 + 0][m] = l0;
                As_hi[kq * 2 + 1][m] = h1; As_lo[kq * 2 + 1][m] = l1;
            }
        }
        {
#pragma unroll
            for (int p2 = 0; p2 < 2; p2++) {
                int tt = t + 256 * p2;
                int pr = tt >> 5, nq = tt & 31;
                float4 b0 = *(const float4*)&B[(size_t)(k0 + 2 * pr) * ldb + n0 + nq * 4];
                float4 b1 = *(const float4*)&B[(size_t)(k0 + 2 * pr + 1) * ldb + n0 + nq * 4];
                uint32_t h, l;
                split2(b0.x, b1.x, h, l); Bs_hi[pr][nq * 4 + 0] = h; Bs_lo[pr][nq * 4 + 0] = l;
                split2(b0.y, b1.y, h, l); Bs_hi[pr][nq * 4 + 1] = h; Bs_lo[pr][nq * 4 + 1] = l;
                split2(b0.z, b1.z, h, l); Bs_hi[pr][nq * 4 + 2] = h; Bs_lo[pr][nq * 4 + 2] = l;
                split2(b0.w, b1.w, h, l); Bs_hi[pr][nq * 4 + 3] = h; Bs_lo[pr][nq * 4 + 3] = l;
            }
        }
        __syncthreads();

#pragma unroll
        for (int kk = 0; kk < 2; kk++) {
            int p0 = kk * 8 + lq;
            uint32_t ah[4][4], al[4][4], bh[4][2], bl[4][2];
#pragma unroll
            for (int mi = 0; mi < 4; mi++) {
                int r = wm + mi * 16 + lr;
                ah[mi][0] = As_hi[p0][r];     al[mi][0] = As_lo[p0][r];
                ah[mi][1] = As_hi[p0][r + 8]; al[mi][1] = As_lo[p0][r + 8];
                ah[mi][2] = As_hi[p0 + 4][r];     al[mi][2] = As_lo[p0 + 4][r];
                ah[mi][3] = As_hi[p0 + 4][r + 8]; al[mi][3] = As_lo[p0 + 4][r + 8];
            }
#pragma unroll
            for (int ni = 0; ni < 4; ni++) {
                int c = wn + ni * 8 + lr;
                bh[ni][0] = Bs_hi[p0][c];     bl[ni][0] = Bs_lo[p0][c];
                bh[ni][1] = Bs_hi[p0 + 4][c]; bl[ni][1] = Bs_lo[p0 + 4][c];
            }
#pragma unroll
            for (int mi = 0; mi < 4; mi++)
#pragma unroll
                for (int ni = 0; ni < 4; ni++) {
                    mma_bf16(acc[mi][ni], ah[mi][0], ah[mi][1], ah[mi][2], ah[mi][3],
                             bh[ni][0], bh[ni][1]);
                    mma_bf16(acc[mi][ni], ah[mi][0], ah[mi][1], ah[mi][2], ah[mi][3],
                             bl[ni][0], bl[ni][1]);
                    mma_bf16(acc[mi][ni], al[mi][0], al[mi][1], al[mi][2], al[mi][3],
                             bh[ni][0], bh[ni][1]);
                }
        }
        __syncthreads();
    }

#pragma unroll
    for (int mi = 0; mi < 4; mi++) {
        int r0 = m0 + wm + mi * 16 + lr;
        int r1 = r0 + 8;
#pragma unroll
        for (int ni = 0; ni < 4; ni++) {
            int c0 = n0 + wn + ni * 8 + lq * 2;
            int c1 = c0 + 1;
            float v00 = acc[mi][ni][0];
            float v01 = acc[mi][ni][1];
            float v10 = acc[mi][ni][2];
            float v11 = acc[mi][ni][3];
            if (bias) { v00 += bias[c0]; v01 += bias[c1]; v10 += bias[c0]; v11 += bias[c1]; }
            if (add) {
                v00 += addScale * add[(size_t)r0 * ldc + c0];
                v01 += addScale * add[(size_t)r0 * ldc + c1];
                v10 += addScale * add[(size_t)r1 * ldc + c0];
                v11 += addScale * add[(size_t)r1 * ldc + c1];
            }
            C[(size_t)r0 * ldc + c0] = v00;
            C[(size_t)r0 * ldc + c1] = v01;
            C[(size_t)r1 * ldc + c0] = v10;
            C[(size_t)r1 * ldc + c1] = v11;
        }
    }
}

__global__ __launch_bounds__(256) void tc_gemm(
    const float* __restrict__ A, int lda,
    const float* __restrict__ B, int ldb,
    float* __restrict__ C, int ldc,
    const float* __restrict__ bias,
    const float* __restrict__ add, float addScale,
    int K) {
    __shared__ uint32_t As_hi[16][LDg], As_lo[16][LDg];
    __shared__ uint32_t Bs_hi[16][LDg], Bs_lo[16][LDg];
    gemm_body(A, lda, B, ldb, C, ldc, bias, add, addScale, K,
              blockIdx.y * BM, blockIdx.x * BN, As_hi, As_lo, Bs_hi, Bs_lo);
}

// batched QKV projection: z selects {Wq,Wk,Wv}
__global__ __launch_bounds__(256) void tc_gemm3(
    const float* __restrict__ A, int lda,
    const float* __restrict__ B0, const float* __restrict__ B1, const float* __restrict__ B2,
    int ldb,
    float* __restrict__ C0, float* __restrict__ C1, float* __restrict__ C2,
    int ldc,
    const float* __restrict__ bias0, const float* __restrict__ bias1, const float* __restrict__ bias2,
    int K) {
    __shared__ uint32_t As_hi[16][LDg], As_lo[16][LDg];
    __shared__ uint32_t Bs_hi[16][LDg], Bs_lo[16][LDg];
    int z = blockIdx.z;
    const float* B = (z == 0) ? B0 : (z == 1) ? B1 : B2;
    float* C = (z == 0) ? C0 : (z == 1) ? C1 : C2;
    const float* bias = (z == 0) ? bias0 : (z == 1) ? bias1 : bias2;
    gemm_body(A, lda, B, ldb, C, ldc, bias, nullptr, 0.f, K,
              blockIdx.y * BM, blockIdx.x * BN, As_hi, As_lo, Bs_hi, Bs_lo);
}

// ---------------- fused flash attention (split-bf16, register P) ----------------
// Grid: (32 row-blocks, 8 heads). Block: 256 threads (8 warps x 16 rows).
#define FBC 64
#define KLD 72   // stride (words) for K/V pair arrays [32][72]
#define QLD 132  // Q staging stride (floats)

#define OFF_KHI 0
#define OFF_KLO (OFF_KHI + 32 * KLD)
#define OFF_VHI (OFF_KLO + 32 * KLD)
#define OFF_VLO (OFF_VHI + 32 * KLD)
#define FLASH_WORDS (OFF_VLO + 32 * KLD)

__global__ __launch_bounds__(256, 1) void flash_k(
    const float* __restrict__ Q, const float* __restrict__ Km,
    const float* __restrict__ Vm, const float* __restrict__ GV,
    float* __restrict__ CTX) {
    extern __shared__ uint32_t sm[];
    uint32_t* Khi = sm + OFF_KHI;
    uint32_t* Klo = sm + OFF_KLO;
    uint32_t* Vhi = sm + OFF_VHI;
    uint32_t* Vlo = sm + OFF_VLO;
    float* Qst = (float*)sm;   // [64][QLD], overlays K/V region pre-loop

    const int t = threadIdx.x, lane = t & 31, warp = t >> 5;
    const int lq = lane & 3, lr = lane >> 2;
    const int h = blockIdx.y;
    const int r0 = blockIdx.x * 128;
    const int wr0 = warp * 16 + lr;

    // ---- stage Q into Qst[d][row]
    {
        int row = t >> 1;
        int dbase = (t & 1) * 32;
        const float* src = Q + (size_t)(r0 + row) * NHID + h * DKh + dbase;
#pragma unroll
        for (int i = 0; i < 8; i++) {
            float4 a = *(const float4*)(src + i * 4);
            Qst[(dbase + i * 4 + 0) * QLD + row] = a.x;
            Qst[(dbase + i * 4 + 1) * QLD + row] = a.y;
            Qst[(dbase + i * 4 + 2) * QLD + row] = a.z;
            Qst[(dbase + i * 4 + 3) * QLD + row] = a.w;
        }
    }
    __syncthreads();

    // ---- build Q fragments (scaled by 1/8), bf16 hi/lo
    uint32_t qh[4][4], ql[4][4];
#pragma unroll
    for (int s = 0; s < 4; s++) {
        int pa = s * 8 + lq;
#pragma unroll
        for (int half = 0; half < 2; half++) {
            int p = pa + half * 4;
            float x0 = Qst[(2 * p + 0) * QLD + wr0] * 0.125f;
            float x1 = Qst[(2 * p + 1) * QLD + wr0] * 0.125f;
            float y0 = Qst[(2 * p + 0) * QLD + wr0 + 8] * 0.125f;
            float y1 = Qst[(2 * p + 1) * QLD + wr0 + 8] * 0.125f;
            split2(x0, x1, qh[s][half * 2 + 0], ql[s][half * 2 + 0]);
            split2(y0, y1, qh[s][half * 2 + 1], ql[s][half * 2 + 1]);
        }
    }
    __syncthreads();

    float oacc[8][4];
#pragma unroll
    for (int ni = 0; ni < 8; ni++)
#pragma unroll
        for (int r = 0; r < 4; r++) oacc[ni][r] = 0.f;
    float m0 = -INFINITY, m1 = -INFINITY, l0 = 0.f, l1 = 0.f;

    // prefetch registers
    const int key = t & 63, dbase2 = (t >> 6) * 16;
    float4 kf[4], vf0[2], vf1[2];
    {
        const float* kp = Km + (size_t)key * NHID + h * DKh + dbase2;
#pragma unroll
        for (int i = 0; i < 4; i++) kf[i] = *(const float4*)(kp + i * 4);
#pragma unroll
        for (int p2 = 0; p2 < 2; p2++) {
            int tt = t + 256 * p2;
            int kp2 = tt >> 4, dg = tt & 15;
            const float* v0p = Vm + (size_t)(2 * kp2) * NHID + h * DKh + dg * 4;
            vf0[p2] = *(const float4*)v0p;
            vf1[p2] = *(const float4*)(v0p + NHID);
        }
    }

    for (int cb = 0; cb < Nn; cb += FBC) {
        // ---- store prefetched K/V (bf16 hi/lo) into smem
        {
#pragma unroll
            for (int i = 0; i < 4; i++) {
                int p = (dbase2 + i * 4) >> 1;
                uint32_t h0, lo0, h1, lo1;
                split2(kf[i].x, kf[i].y, h0, lo0);
                split2(kf[i].z, kf[i].w, h1, lo1);
                Khi[(p + 0) * KLD + key] = h0; Klo[(p + 0) * KLD + key] = lo0;
                Khi[(p + 1) * KLD + key] = h1; Klo[(p + 1) * KLD + key] = lo1;
            }
#pragma unroll
            for (int p2 = 0; p2 < 2; p2++) {
                int tt = t + 256 * p2;
                int kp2 = tt >> 4, dg = tt & 15;
                uint32_t hh, ll;
                split2(vf0[p2].x, vf1[p2].x, hh, ll); Vhi[kp2 * KLD + dg * 4 + 0] = hh; Vlo[kp2 * KLD + dg * 4 + 0] = ll;
                split2(vf0[p2].y, vf1[p2].y, hh, ll); Vhi[kp2 * KLD + dg * 4 + 1] = hh; Vlo[kp2 * KLD + dg * 4 + 1] = ll;
                split2(vf0[p2].z, vf1[p2].z, hh, ll); Vhi[kp2 * KLD + dg * 4 + 2] = hh; Vlo[kp2 * KLD + dg * 4 + 2] = ll;
                split2(vf0[p2].w, vf1[p2].w, hh, ll); Vhi[kp2 * KLD + dg * 4 + 3] = hh; Vlo[kp2 * KLD + dg * 4 + 3] = ll;
            }
        }
        __syncthreads();

        // ---- prefetch next block (LDGs in flight during compute)
        if (cb + FBC < Nn) {
            const float* kp = Km + (size_t)(cb + FBC + key) * NHID + h * DKh + dbase2;
#pragma unroll
            for (int i = 0; i < 4; i++) kf[i] = *(const float4*)(kp + i * 4);
#pragma unroll
            for (int p2 = 0; p2 < 2; p2++) {
                int tt = t + 256 * p2;
                int kp2 = tt >> 4, dg = tt & 15;
                const float* v0p = Vm + (size_t)(cb + FBC + 2 * kp2) * NHID + h * DKh + dg * 4;
                vf0[p2] = *(const float4*)v0p;
                vf1[p2] = *(const float4*)(v0p + NHID);
            }
        }

        // ---- S = (Q/8) @ K^T
        float sacc[8][4];
#pragma unroll
        for (int ni = 0; ni < 8; ni++)
#pragma unroll
            for (int r = 0; r < 4; r++) sacc[ni][r] = 0.f;
#pragma unroll
        for (int s = 0; s < 4; s++) {
            int p0 = s * 8 + lq;
#pragma unroll
            for (int ni = 0; ni < 8; ni++) {
                int c = ni * 8 + lr;
                uint32_t b0 = Khi[p0 * KLD + c], b1 = Khi[(p0 + 4) * KLD + c];
                uint32_t c0 = Klo[p0 * KLD + c], c1 = Klo[(p0 + 4) * KLD + c];
                mma_bf16(sacc[ni], qh[s][0], qh[s][1], qh[s][2], qh[s][3], b0, b1);
                mma_bf16(sacc[ni], qh[s][0], qh[s][1], qh[s][2], qh[s][3], c0, c1);
                mma_bf16(sacc[ni], ql[s][0], ql[s][1], ql[s][2], ql[s][3], b0, b1);
            }
        }

        // ---- online softmax (register-resident)
        float bm0 = -INFINITY, bm1 = -INFINITY;
#pragma unroll
        for (int ni = 0; ni < 8; ni++) {
            bm0 = fmaxf(bm0, fmaxf(sacc[ni][0], sacc[ni][1]));
            bm1 = fmaxf(bm1, fmaxf(sacc[ni][2], sacc[ni][3]));
        }
        bm0 = fmaxf(bm0, __shfl_xor_sync(0xffffffffu, bm0, 1));
        bm0 = fmaxf(bm0, __shfl_xor_sync(0xffffffffu, bm0, 2));
        bm1 = fmaxf(bm1, __shfl_xor_sync(0xffffffffu, bm1, 1));
        bm1 = fmaxf(bm1, __shfl_xor_sync(0xffffffffu, bm1, 2));
        float mn0 = fmaxf(m0, bm0), mn1 = fmaxf(m1, bm1);
        float cf0 = fexp(m0 - mn0), cf1 = fexp(m1 - mn1);
        float s0 = 0.f, s1 = 0.f;
#pragma unroll
        for (int ni = 0; ni < 8; ni++) {
            sacc[ni][0] = fexp(sacc[ni][0] - mn0);
            sacc[ni][1] = fexp(sacc[ni][1] - mn0);
            sacc[ni][2] = fexp(sacc[ni][2] - mn1);
            sacc[ni][3] = fexp(sacc[ni][3] - mn1);
            s0 += sacc[ni][0] + sacc[ni][1];
            s1 += sacc[ni][2] + sacc[ni][3];
        }
        s0 += __shfl_xor_sync(0xffffffffu, s0, 1);
        s0 += __shfl_xor_sync(0xffffffffu, s0, 2);
        s1 += __shfl_xor_sync(0xffffffffu, s1, 1);
        s1 += __shfl_xor_sync(0xffffffffu, s1, 2);
        l0 = l0 * cf0 + s0;
        l1 = l1 * cf1 + s1;
        m0 = mn0; m1 = mn1;
#pragma unroll
        for (int ni = 0; ni < 8; ni++) {
            oacc[ni][0] *= cf0; oacc[ni][1] *= cf0;
            oacc[ni][2] *= cf1; oacc[ni][3] *= cf1;
        }

        // ---- O += P @ V with P taken straight from registers
#pragma unroll
        for (int s = 0; s < 4; s++) {
            uint32_t a0, a1, a2, a3, e0, e1, e2, e3;
            split2(sacc[2 * s][0],     sacc[2 * s][1],     a0, e0);
            split2(sacc[2 * s][2],     sacc[2 * s][3],     a1, e1);
            split2(sacc[2 * s + 1][0], sacc[2 * s + 1][1], a2, e2);
            split2(sacc[2 * s + 1][2], sacc[2 * s + 1][3], a3, e3);
            int p0 = s * 8 + lq;
#pragma unroll
            for (int ni = 0; ni < 8; ni++) {
                int c = ni * 8 + lr;
                uint32_t b0 = Vhi[p0 * KLD + c], b1 = Vhi[(p0 + 4) * KLD + c];
                uint32_t c0 = Vlo[p0 * KLD + c], c1 = Vlo[(p0 + 4) * KLD + c];
                mma_bf16(oacc[ni], a0, a1, a2, a3, b0, b1);
                mma_bf16(oacc[ni], a0, a1, a2, a3, c0, c1);
                mma_bf16(oacc[ni], e0, e1, e2, e3, b0, b1);
            }
        }
        __syncthreads();
    }

    // ---- epilogue: ctx = 0.5*O/l + 0.5*gv
    float inv0 = 0.5f / l0, inv1 = 0.5f / l1;
#pragma unroll
    for (int ni = 0; ni < 8; ni++) {
        int c = ni * 8 + lq * 2;
        size_t o0 = (size_t)(r0 + wr0) * NHID + h * DKh + c;
        size_t o1 = (size_t)(r0 + wr0 + 8) * NHID + h * DKh + c;
        float2 gv0 = *(const float2*)&GV[o0];
        float2 gv1 = *(const float2*)&GV[o1];
        float2 w0, w1;
        w0.x = oacc[ni][0] * inv0 + 0.5f * gv0.x;
        w0.y = oacc[ni][1] * inv0 + 0.5f * gv0.y;
        w1.x = oacc[ni][2] * inv1 + 0.5f * gv1.x;
        w1.y = oacc[ni][3] * inv1 + 0.5f * gv1.y;
        *(float2*)&CTX[o0] = w0;
        *(float2*)&CTX[o1] = w1;
    }
}

// ---------------- layernorm + prelu ----------------
__global__ void ln_prelu_k(const float* __restrict__ in, float* __restrict__ out,
                           const float* __restrict__ g, const float* __restrict__ b,
                           const float* __restrict__ aptr) {
    int t = threadIdx.x;
    const float* row = in + (size_t)blockIdx.x * NHID;
    float x0 = row[t], x1 = row[t + 256];
    __shared__ float red[256];
    red[t] = x0 + x1; __syncthreads();
    for (int w = 128; w > 0; w >>= 1) { if (t < w) red[t] += red[t + w]; __syncthreads(); }
    float mu = red[0] * (1.0f / NHID);
    __syncthreads();
    float d0 = x0 - mu, d1 = x1 - mu;
    red[t] = d0 * d0 + d1 * d1; __syncthreads();
    for (int w = 128; w > 0; w >>= 1) { if (t < w) red[t] += red[t + w]; __syncthreads(); }
    float inv = rsqrtf(red[0] * (1.0f / NHID) + 1e-5f);
    float a = *aptr;
    float y0 = d0 * inv * g[t] + b[t];
    float y1 = d1 * inv * g[t + 256] + b[t + 256];
    float* orow = out + (size_t)blockIdx.x * NHID;
    orow[t] = (y0 >= 0.f) ? y0 : a * y0;
    orow[t + 256] = (y1 >= 0.f) ? y1 : a * y1;
}

// ---------------- classifier + log_softmax ----------------
__global__ void cls_k(const float* __restrict__ x, const float* __restrict__ w,
                      const float* __restrict__ bias, float* __restrict__ out) {
    __shared__ float xs[NHID];
    __shared__ float lg[NCLASS];
    int t = threadIdx.x;  // 128
    const float* row = x + (size_t)blockIdx.x * NHID;
    for (int i = t; i < NHID; i += 128) xs[i] = row[i];
    __syncthreads();
    if (t < NCLASS) {
        float s = bias[t];
        for (int k = 0; k < NHID; k++) s += xs[k] * w[k * NCLASS + t];
        lg[t] = s;
    }
    __syncthreads();
    if (t < NCLASS) {
        float mx = -INFINITY;
        for (int c = 0; c < NCLASS; c++) mx = fmaxf(mx, lg[c]);
        float sum = 0.f;
        for (int c = 0; c < NCLASS; c++) sum += __expf(lg[c] - mx);
        out[(size_t)blockIdx.x * NCLASS + t] = lg[t] - mx - logf(sum);
    }
}

// ---------------- host launcher ----------------
extern "C" void kernel_launch(void* const* d_in, const int* in_sizes, int n_in,
                              void* d_out, int out_size) {
    const float* X0     = (const float*)d_in[0];
    const float* Hm     = (const float*)d_in[1];
    const float* w_feat = (const float*)d_in[2];
    const float* b_feat = (const float*)d_in[3];
    const float* Wq     = (const float*)d_in[4];
    const float* bq     = (const float*)d_in[5];
    const float* Wk     = (const float*)d_in[6];
    const float* bk     = (const float*)d_in[7];
    const float* Wv     = (const float*)d_in[8];
    const float* bv     = (const float*)d_in[9];
    const float* Wo     = (const float*)d_in[10];
    const float* bo     = (const float*)d_in[11];
    const float* ln_g   = (const float*)d_in[12];
    const float* ln_b   = (const float*)d_in[13];
    const float* prelu_a= (const float*)d_in[14];
    const float* w_cls  = (const float*)d_in[15];
    const float* b_cls  = (const float*)d_in[16];
    float* out = (float*)d_out;

    float *x_, *q_, *k_, *v_, *gv_, *ctx_, *pre_;
    cudaGetSymbolAddress((void**)&x_, g_x);
    cudaGetSymbolAddress((void**)&q_, g_q);
    cudaGetSymbolAddress((void**)&k_, g_k);
    cudaGetSymbolAddress((void**)&v_, g_v);
    cudaGetSymbolAddress((void**)&gv_, g_gv);
    cudaGetSymbolAddress((void**)&ctx_, g_ctx);
    cudaGetSymbolAddress((void**)&pre_, g_pre);

    const int flashSmem = FLASH_WORDS * 4;
    cudaFuncSetAttribute(flash_k, cudaFuncAttributeMaxDynamicSharedMemorySize, flashSmem);

    row_sums_k<<<Nn, 256>>>(Hm);
    col_part_k<<<dim3(Ee / 256, 32), 256>>>(Hm);
    finalize_deg_k<<<Nn / 256, 256>>>();
    rowlist_k<<<Nn / 8, 256>>>(Hm);
    collist_k<<<Ee / 256, 256>>>(Hm);

    dim3 gHid(NHID / BN, Nn / BM);

    tc_gemm<<<gHid, 256>>>(X0, NHID, w_feat, NHID, x_, NHID, b_feat, nullptr, 0.f, NHID);

    for (int i = 0; i < NLAYER; i++) {
        const float* Wqi = Wq + (size_t)i * NHID * NHID;
        const float* Wki = Wk + (size_t)i * NHID * NHID;
        const float* Wvi = Wv + (size_t)i * NHID * NHID;
        const float* Woi = Wo + (size_t)i * NHID * NHID;

        // batched Q/K/V projections
        tc_gemm3<<<dim3(NHID / BN, Nn / BM, 3), 256>>>(
            x_, NHID, Wqi, Wki, Wvi, NHID, q_, k_, v_, NHID,
            bq + i * NHID, bk + i * NHID, bv + i * NHID, NHID);

        edge_gather_k<<<Ee, 128>>>(v_);
        node_gather_k<<<Nn, 128>>>();

        flash_k<<<dim3(32, 8), 256, flashSmem>>>(q_, k_, v_, gv_, ctx_);

        tc_gemm<<<gHid, 256>>>(ctx_, NHID, Woi, NHID, pre_, NHID, bo + i * NHID, x_, 1.f, NHID);

        ln_prelu_k<<<Nn, 256>>>(pre_, x_, ln_g + i * NHID, ln_b + i * NHID, prelu_a + i);
    }

    cls_k<<<Nn, 128>>>(x_, w_cls, b_cls, out);
}